// round 1
// baseline (speedup 1.0000x reference)
#include <cuda_runtime.h>
#include <cuda_bf16.h>
#include <math.h>

// Problem dims (fixed)
#define HH 16
#define EE 1024
#define DD 64
#define MM 64
#define OO 1024
#define SS 2048

// Scratch (device globals: allocation-free per harness rules)
__device__ float g_Q[HH * SS * DD];   // [H][S][D]
__device__ float g_K[HH * SS * DD];   // [H][S][D]
__device__ float g_V[HH * SS * MM];   // [H][S][M]
__device__ float g_O[SS * HH * MM];   // [S][H*M] concat layout

// ---------------------------------------------------------------------------
// Generic 64x64 output-tile fp32 GEMM body: C = A[M,K] @ B[K,N] + bias
// 256 threads, BK=16, 4x4 register micro-tile per thread.
// ---------------------------------------------------------------------------
__device__ __forceinline__ void gemm64_body(
    const float* __restrict__ A, int lda,
    const float* __restrict__ B, int ldb,
    const float* __restrict__ bias,
    float* __restrict__ C, int ldc,
    int Kdim, int row0, int col0)
{
    __shared__ float As[16][64];       // transposed: As[k][m]
    __shared__ float Bs[16][68];       // padded

    const int tid = threadIdx.x;
    const int tx = tid & 15;           // 0..15 -> col group
    const int ty = tid >> 4;           // 0..15 -> row group

    const int arow  = tid >> 2;        // 0..63
    const int acol4 = (tid & 3) * 4;   // 0,4,8,12
    const int brow  = tid >> 4;        // 0..15
    const int bcol4 = (tid & 15) * 4;  // 0..60

    float acc[4][4];
#pragma unroll
    for (int i = 0; i < 4; i++)
#pragma unroll
        for (int j = 0; j < 4; j++) acc[i][j] = 0.f;

    for (int k0 = 0; k0 < Kdim; k0 += 16) {
        float4 av = *(const float4*)&A[(size_t)(row0 + arow) * lda + k0 + acol4];
        As[acol4 + 0][arow] = av.x;
        As[acol4 + 1][arow] = av.y;
        As[acol4 + 2][arow] = av.z;
        As[acol4 + 3][arow] = av.w;
        *(float4*)&Bs[brow][bcol4] =
            *(const float4*)&B[(size_t)(k0 + brow) * ldb + col0 + bcol4];
        __syncthreads();

#pragma unroll
        for (int k = 0; k < 16; k++) {
            float4 a4 = *(const float4*)&As[k][ty * 4];
            float4 b4 = *(const float4*)&Bs[k][tx * 4];
            float ar[4] = {a4.x, a4.y, a4.z, a4.w};
            float br[4] = {b4.x, b4.y, b4.z, b4.w};
#pragma unroll
            for (int i = 0; i < 4; i++)
#pragma unroll
                for (int j = 0; j < 4; j++) acc[i][j] += ar[i] * br[j];
        }
        __syncthreads();
    }

#pragma unroll
    for (int i = 0; i < 4; i++) {
        int r = row0 + ty * 4 + i;
#pragma unroll
        for (int j = 0; j < 4; j++) {
            int c = col0 + tx * 4 + j;
            C[(size_t)r * ldc + c] = acc[i][j] + bias[c];
        }
    }
}

// ---------------------------------------------------------------------------
// Kernel 1: QKV projections.  grid = (S/64, H, 3), block = 256
// kind 0: Q = x @ Wq[h] + bq[h];  kind 1: K = z @ Wk[h] + bk[h];
// kind 2: V = z @ Wv[h] + bv[h]
// ---------------------------------------------------------------------------
__global__ void qkv_kernel(const float* __restrict__ x,
                           const float* __restrict__ z,
                           const float* __restrict__ Wq, const float* __restrict__ bq,
                           const float* __restrict__ Wk, const float* __restrict__ bk,
                           const float* __restrict__ Wv, const float* __restrict__ bv)
{
    const int h    = blockIdx.y;
    const int kind = blockIdx.z;
    const int row0 = blockIdx.x * 64;

    const float* A;
    const float* B;
    const float* bias;
    float* C;
    if (kind == 0) {
        A = x;  B = Wq + (size_t)h * EE * DD; bias = bq + h * DD; C = g_Q + (size_t)h * SS * DD;
    } else if (kind == 1) {
        A = z;  B = Wk + (size_t)h * EE * DD; bias = bk + h * DD; C = g_K + (size_t)h * SS * DD;
    } else {
        A = z;  B = Wv + (size_t)h * EE * MM; bias = bv + h * MM; C = g_V + (size_t)h * SS * MM;
    }
    gemm64_body(A, EE, B, DD, bias, C, DD, EE, row0, 0);
}

// ---------------------------------------------------------------------------
// Kernel 2: flash attention per head.  grid = (S/64, H), block = 256
// Online softmax over 64-key tiles; O accumulated in registers.
// ---------------------------------------------------------------------------
__global__ void attn_kernel(const int* __restrict__ mask)
{
    extern __shared__ float sm[];
    float* Qs   = sm;                  // 64 x 68
    float* Ks   = Qs + 64 * 68;        // 64 x 68
    float* Vs   = Ks + 64 * 68;        // 64 x 68
    float* Ps   = Vs + 64 * 68;        // 64 x 68
    float* red  = Ps + 64 * 68;        // 64 x 16
    float* mrow = red + 64 * 16;       // 64
    float* lrow = mrow + 64;           // 64
    float* arow = lrow + 64;           // 64

    const int h  = blockIdx.y;
    const int q0 = blockIdx.x * 64;
    const int tid = threadIdx.x;
    const int tx = tid & 15;
    const int ty = tid >> 4;

    const float* Qg = g_Q + (size_t)h * SS * DD;
    const float* Kg = g_K + (size_t)h * SS * DD;
    const float* Vg = g_V + (size_t)h * SS * MM;

    // Load Q tile (64x64), each thread 4 float4s
    {
        int row = tid >> 4;            // 0..15
        int col4 = (tid & 15) * 4;
#pragma unroll
        for (int i = 0; i < 4; i++) {
            int r = row + i * 16;
            *(float4*)&Qs[r * 68 + col4] =
                *(const float4*)&Qg[(size_t)(q0 + r) * DD + col4];
        }
    }
    if (tid < 64) { mrow[tid] = -INFINITY; lrow[tid] = 0.f; }

    float o[4][4];
#pragma unroll
    for (int i = 0; i < 4; i++)
#pragma unroll
        for (int j = 0; j < 4; j++) o[i][j] = 0.f;

    __syncthreads();

    for (int t0 = 0; t0 < SS; t0 += 64) {
        // Load K,V tiles
        {
            int row = tid >> 4;
            int col4 = (tid & 15) * 4;
#pragma unroll
            for (int i = 0; i < 4; i++) {
                int r = row + i * 16;
                *(float4*)&Ks[r * 68 + col4] =
                    *(const float4*)&Kg[(size_t)(t0 + r) * DD + col4];
                *(float4*)&Vs[r * 68 + col4] =
                    *(const float4*)&Vg[(size_t)(t0 + r) * MM + col4];
            }
        }
        __syncthreads();

        // S = Q @ K^T (scaled) for this thread's 4x4 fragment
        float s[4][4];
#pragma unroll
        for (int i = 0; i < 4; i++)
#pragma unroll
            for (int j = 0; j < 4; j++) s[i][j] = 0.f;

        for (int d = 0; d < DD; d += 4) {
            float4 q4[4], k4[4];
#pragma unroll
            for (int i = 0; i < 4; i++)
                q4[i] = *(const float4*)&Qs[(ty * 4 + i) * 68 + d];
#pragma unroll
            for (int j = 0; j < 4; j++)
                k4[j] = *(const float4*)&Ks[(tx * 4 + j) * 68 + d];
#pragma unroll
            for (int i = 0; i < 4; i++)
#pragma unroll
                for (int j = 0; j < 4; j++)
                    s[i][j] += q4[i].x * k4[j].x + q4[i].y * k4[j].y +
                               q4[i].z * k4[j].z + q4[i].w * k4[j].w;
        }

        // scale + mask + row-max partials
#pragma unroll
        for (int i = 0; i < 4; i++) {
            int rg = q0 + ty * 4 + i;
            float lm = -INFINITY;
#pragma unroll
            for (int j = 0; j < 4; j++) {
                int cg = t0 + tx * 4 + j;
                float v = s[i][j] * 0.125f;      // 1/sqrt(64)
                if (mask[(size_t)rg * SS + cg] == 0) v = -INFINITY;
                s[i][j] = v;
                lm = fmaxf(lm, v);
            }
            red[(ty * 4 + i) * 16 + tx] = lm;
        }
        __syncthreads();

        if (tid < 64) {
            float nm = mrow[tid];
            for (int t = 0; t < 16; t++) nm = fmaxf(nm, red[tid * 16 + t]);
            float mo = mrow[tid];
            float a = (nm > -INFINITY) ? __expf(mo - nm) : 0.f;
            arow[tid] = a;
            mrow[tid] = nm;
        }
        __syncthreads();

        // P = exp(S - m), write to smem, row-sum partials
#pragma unroll
        for (int i = 0; i < 4; i++) {
            int rr = ty * 4 + i;
            float mr = mrow[rr];
            float ls = 0.f;
#pragma unroll
            for (int j = 0; j < 4; j++) {
                float sv = s[i][j];
                float p = (sv > -INFINITY) ? __expf(sv - mr) : 0.f;
                Ps[rr * 68 + tx * 4 + j] = p;
                ls += p;
            }
            red[rr * 16 + tx] = ls;
        }
        __syncthreads();

        if (tid < 64) {
            float sum = 0.f;
            for (int t = 0; t < 16; t++) sum += red[tid * 16 + t];
            lrow[tid] = lrow[tid] * arow[tid] + sum;
        }

        // O = O*alpha + P @ V
        float al[4];
#pragma unroll
        for (int i = 0; i < 4; i++) {
            al[i] = arow[ty * 4 + i];
#pragma unroll
            for (int j = 0; j < 4; j++) o[i][j] *= al[i];
        }
        for (int t = 0; t < 64; t++) {
            float4 v4 = *(const float4*)&Vs[t * 68 + tx * 4];
#pragma unroll
            for (int i = 0; i < 4; i++) {
                float p = Ps[(ty * 4 + i) * 68 + t];
                o[i][0] += p * v4.x;
                o[i][1] += p * v4.y;
                o[i][2] += p * v4.z;
                o[i][3] += p * v4.w;
            }
        }
        __syncthreads();
    }

    // Normalize and write to concat layout [S, H*M]
#pragma unroll
    for (int i = 0; i < 4; i++) {
        int rr = ty * 4 + i;
        float inv = 1.f / lrow[rr];
#pragma unroll
        for (int j = 0; j < 4; j++) {
            g_O[(size_t)(q0 + rr) * (HH * MM) + h * MM + tx * 4 + j] = o[i][j] * inv;
        }
    }
}

// ---------------------------------------------------------------------------
// Kernel 3: output projection.  grid = (S/64, O/64), block = 256
// out = g_O [S, H*M] @ W0 [H*M, O] + b0
// ---------------------------------------------------------------------------
__global__ void out_proj_kernel(const float* __restrict__ W0,
                                const float* __restrict__ b0,
                                float* __restrict__ out)
{
    gemm64_body(g_O, HH * MM, W0, OO, b0, out, OO, HH * MM,
                blockIdx.x * 64, blockIdx.y * 64);
}

// ---------------------------------------------------------------------------
extern "C" void kernel_launch(void* const* d_in, const int* in_sizes, int n_in,
                              void* d_out, int out_size)
{
    const float* x    = (const float*)d_in[0];
    const float* z    = (const float*)d_in[1];
    const int*   mask = (const int*)  d_in[2];
    const float* Wq   = (const float*)d_in[3];
    const float* bq   = (const float*)d_in[4];
    const float* Wk   = (const float*)d_in[5];
    const float* bk   = (const float*)d_in[6];
    const float* Wv   = (const float*)d_in[7];
    const float* bv   = (const float*)d_in[8];
    const float* W0   = (const float*)d_in[9];
    const float* b0   = (const float*)d_in[10];
    float* out = (float*)d_out;

    // 1) QKV projections
    qkv_kernel<<<dim3(SS / 64, HH, 3), 256>>>(x, z, Wq, bq, Wk, bk, Wv, bv);

    // 2) flash attention
    size_t smem = (4 * 64 * 68 + 64 * 16 + 3 * 64) * sizeof(float);
    cudaFuncSetAttribute(attn_kernel,
                         cudaFuncAttributeMaxDynamicSharedMemorySize, (int)smem);
    attn_kernel<<<dim3(SS / 64, HH), 256, smem>>>(mask);

    // 3) output projection
    out_proj_kernel<<<dim3(SS / 64, OO / 64), 256>>>(W0, b0, out);
}

// round 2
// speedup vs baseline: 2.4726x; 2.4726x over previous
#include <cuda_runtime.h>
#include <cuda_bf16.h>
#include <math.h>

// Problem dims (fixed)
#define HH 16
#define EE 1024
#define DD 64
#define MM 64
#define OO 1024
#define SS 2048

// Scratch
__device__ float g_Q[HH * SS * DD];   // [H][S][D]
__device__ float g_K[HH * SS * DD];
__device__ float g_V[HH * SS * MM];
__device__ float g_O[SS * HH * MM];   // [S][H*M]

// ---------------------------------------------------------------------------
// helpers
// ---------------------------------------------------------------------------
__device__ __forceinline__ unsigned cvt_tf32(float v) {
    unsigned u;
    asm("cvt.rna.tf32.f32 %0, %1;" : "=r"(u) : "f"(v));
    return u;
}
__device__ __forceinline__ float tf32f(float v) {
    return __uint_as_float(cvt_tf32(v));
}
__device__ __forceinline__ void mma8(float* d, const unsigned* a, const unsigned* b) {
    asm volatile(
        "mma.sync.aligned.m16n8k8.row.col.f32.tf32.tf32.f32 "
        "{%0,%1,%2,%3}, {%4,%5,%6,%7}, {%8,%9}, {%0,%1,%2,%3};"
        : "+f"(d[0]), "+f"(d[1]), "+f"(d[2]), "+f"(d[3])
        : "r"(a[0]), "r"(a[1]), "r"(a[2]), "r"(a[3]), "r"(b[0]), "r"(b[1]));
}

// ---------------------------------------------------------------------------
// Split-tf32 GEMM: C[128 x 64] tile of A[M,1024] @ B[1024,N] + bias
// 256 threads. 3xTF32 (hi*hi + hi*lo + lo*hi) => near-fp32 accuracy.
// smem layout (floats): Ah[128][36] Al[128][36] Bh[32][72] Bl[32][72]
// ---------------------------------------------------------------------------
#define PROJ_SMEM_FLOATS (128*36*2 + 32*72*2)

__device__ __forceinline__ void gemm_split_body(
    const float* __restrict__ A, int lda,
    const float* __restrict__ B, int ldb,
    const float* __restrict__ bias,     // already offset to this col tile
    float* __restrict__ C, int ldc,
    int row0, int col0)
{
    extern __shared__ float sm[];
    float* Ah = sm;                 // [128][36]
    float* Al = Ah + 128 * 36;
    float* Bh = Al + 128 * 36;      // [32][72]
    float* Bl = Bh + 32 * 72;

    const int tid  = threadIdx.x;
    const int lane = tid & 31;
    const int warp = tid >> 5;
    const int gr = lane >> 2;       // 0..7
    const int tc = lane & 3;        // 0..3
    const int wm = (warp >> 1) * 32;  // warp row base (0,32,64,96)
    const int wn = (warp & 1) * 32;   // warp col base (0,32)

    float acc[2][4][4];
#pragma unroll
    for (int mi = 0; mi < 2; mi++)
#pragma unroll
        for (int ni = 0; ni < 4; ni++)
#pragma unroll
            for (int j = 0; j < 4; j++) acc[mi][ni][j] = 0.f;

    const int a_c4 = (tid & 7) * 4;   // 0..28
    const int a_r  = tid >> 3;        // 0..31
    const int b_c4 = (tid & 15) * 4;  // 0..60
    const int b_r  = tid >> 4;        // 0..15

    for (int k0 = 0; k0 < 1024; k0 += 32) {
        // load A 128x32
#pragma unroll
        for (int i = 0; i < 4; i++) {
            int r = a_r + i * 32;
            float4 v = *(const float4*)&A[(size_t)(row0 + r) * lda + k0 + a_c4];
            float h0 = tf32f(v.x), h1 = tf32f(v.y), h2 = tf32f(v.z), h3 = tf32f(v.w);
            Ah[r * 36 + a_c4 + 0] = h0;  Al[r * 36 + a_c4 + 0] = tf32f(v.x - h0);
            Ah[r * 36 + a_c4 + 1] = h1;  Al[r * 36 + a_c4 + 1] = tf32f(v.y - h1);
            Ah[r * 36 + a_c4 + 2] = h2;  Al[r * 36 + a_c4 + 2] = tf32f(v.z - h2);
            Ah[r * 36 + a_c4 + 3] = h3;  Al[r * 36 + a_c4 + 3] = tf32f(v.w - h3);
        }
        // load B 32x64
#pragma unroll
        for (int i = 0; i < 2; i++) {
            int r = b_r + i * 16;
            float4 v = *(const float4*)&B[(size_t)(k0 + r) * ldb + col0 + b_c4];
            float h0 = tf32f(v.x), h1 = tf32f(v.y), h2 = tf32f(v.z), h3 = tf32f(v.w);
            Bh[r * 72 + b_c4 + 0] = h0;  Bl[r * 72 + b_c4 + 0] = tf32f(v.x - h0);
            Bh[r * 72 + b_c4 + 1] = h1;  Bl[r * 72 + b_c4 + 1] = tf32f(v.y - h1);
            Bh[r * 72 + b_c4 + 2] = h2;  Bl[r * 72 + b_c4 + 2] = tf32f(v.z - h2);
            Bh[r * 72 + b_c4 + 3] = h3;  Bl[r * 72 + b_c4 + 3] = tf32f(v.w - h3);
        }
        __syncthreads();

#pragma unroll
        for (int kc = 0; kc < 4; kc++) {
            const int k8 = kc * 8;
            unsigned ah[2][4], al[2][4], bh[4][2], bl[4][2];
#pragma unroll
            for (int mi = 0; mi < 2; mi++) {
                int rb = wm + mi * 16;
                ah[mi][0] = __float_as_uint(Ah[(rb + gr) * 36 + k8 + tc]);
                ah[mi][1] = __float_as_uint(Ah[(rb + gr + 8) * 36 + k8 + tc]);
                ah[mi][2] = __float_as_uint(Ah[(rb + gr) * 36 + k8 + tc + 4]);
                ah[mi][3] = __float_as_uint(Ah[(rb + gr + 8) * 36 + k8 + tc + 4]);
                al[mi][0] = __float_as_uint(Al[(rb + gr) * 36 + k8 + tc]);
                al[mi][1] = __float_as_uint(Al[(rb + gr + 8) * 36 + k8 + tc]);
                al[mi][2] = __float_as_uint(Al[(rb + gr) * 36 + k8 + tc + 4]);
                al[mi][3] = __float_as_uint(Al[(rb + gr + 8) * 36 + k8 + tc + 4]);
            }
#pragma unroll
            for (int ni = 0; ni < 4; ni++) {
                int cb = wn + ni * 8;
                bh[ni][0] = __float_as_uint(Bh[(k8 + tc) * 72 + cb + gr]);
                bh[ni][1] = __float_as_uint(Bh[(k8 + tc + 4) * 72 + cb + gr]);
                bl[ni][0] = __float_as_uint(Bl[(k8 + tc) * 72 + cb + gr]);
                bl[ni][1] = __float_as_uint(Bl[(k8 + tc + 4) * 72 + cb + gr]);
            }
#pragma unroll
            for (int mi = 0; mi < 2; mi++)
#pragma unroll
                for (int ni = 0; ni < 4; ni++) {
                    mma8(acc[mi][ni], ah[mi], bl[ni]);
                    mma8(acc[mi][ni], al[mi], bh[ni]);
                    mma8(acc[mi][ni], ah[mi], bh[ni]);
                }
        }
        __syncthreads();
    }

    // epilogue: C layout c0:(gr, 2tc) c1:(gr, 2tc+1) c2:(gr+8,..) c3
#pragma unroll
    for (int mi = 0; mi < 2; mi++)
#pragma unroll
        for (int ni = 0; ni < 4; ni++) {
            int cl = wn + ni * 8 + 2 * tc;
            int r0 = row0 + wm + mi * 16 + gr;
            float b0v = bias[cl], b1v = bias[cl + 1];
            float2 v0 = {acc[mi][ni][0] + b0v, acc[mi][ni][1] + b1v};
            float2 v1 = {acc[mi][ni][2] + b0v, acc[mi][ni][3] + b1v};
            *(float2*)&C[(size_t)r0 * ldc + col0 + cl] = v0;
            *(float2*)&C[(size_t)(r0 + 8) * ldc + col0 + cl] = v1;
        }
}

// ---------------------------------------------------------------------------
// Kernel 1: QKV projections. grid = (S/128, H, 3)
// ---------------------------------------------------------------------------
__global__ __launch_bounds__(256, 1) void qkv_kernel(
    const float* __restrict__ x, const float* __restrict__ z,
    const float* __restrict__ Wq, const float* __restrict__ bq,
    const float* __restrict__ Wk, const float* __restrict__ bk,
    const float* __restrict__ Wv, const float* __restrict__ bv)
{
    const int h = blockIdx.y, kind = blockIdx.z;
    const int row0 = blockIdx.x * 128;
    const float *A, *B, *bias;
    float* C;
    if (kind == 0) { A = x; B = Wq + (size_t)h*EE*DD; bias = bq + h*DD; C = g_Q + (size_t)h*SS*DD; }
    else if (kind == 1) { A = z; B = Wk + (size_t)h*EE*DD; bias = bk + h*DD; C = g_K + (size_t)h*SS*DD; }
    else { A = z; B = Wv + (size_t)h*EE*MM; bias = bv + h*MM; C = g_V + (size_t)h*SS*MM; }
    gemm_split_body(A, EE, B, DD, bias, C, DD, row0, 0);
}

// ---------------------------------------------------------------------------
// Kernel 3: output projection. grid = (S/128, O/64)
// ---------------------------------------------------------------------------
__global__ __launch_bounds__(256, 1) void out_proj_kernel(
    const float* __restrict__ W0, const float* __restrict__ b0,
    float* __restrict__ out)
{
    gemm_split_body(g_O, HH*MM, W0, OO, b0 + blockIdx.y * 64, out, OO,
                    blockIdx.x * 128, blockIdx.y * 64);
}

// ---------------------------------------------------------------------------
// Kernel 2: flash attention, tf32 MMA. grid = (S/128, H), 256 threads.
// Warp w owns query rows [w*16, w*16+16). Online softmax in C-frag layout.
// smem floats: Qs[128][68] Ks[64][68] Vs[64][72] Ps[128][68]
// ---------------------------------------------------------------------------
#define ATTN_SMEM_FLOATS (128*68 + 64*68 + 64*72 + 128*68)

__global__ __launch_bounds__(256, 1) void attn_kernel(const int* __restrict__ mask)
{
    extern __shared__ float sm[];
    float* Qs = sm;                 // [128][68]
    float* Ks = Qs + 128 * 68;      // [64][68]
    float* Vs = Ks + 64 * 68;       // [64][72]
    float* Ps = Vs + 64 * 72;       // [128][68]

    const int h  = blockIdx.y;
    const int q0 = blockIdx.x * 128;
    const int tid  = threadIdx.x;
    const int lane = tid & 31;
    const int warp = tid >> 5;
    const int gr = lane >> 2, tc = lane & 3;
    const int wr = warp * 16;       // warp's query-row base within tile

    const float* Qg = g_Q + (size_t)h * SS * DD;
    const float* Kg = g_K + (size_t)h * SS * DD;
    const float* Vg = g_V + (size_t)h * SS * MM;

    // load Q tile (tf32)
    {
        int c4 = (tid & 15) * 4;
        int r = tid >> 4;
#pragma unroll
        for (int i = 0; i < 8; i++) {
            int rr = r + i * 16;
            float4 v = *(const float4*)&Qg[(size_t)(q0 + rr) * DD + c4];
            Qs[rr * 68 + c4 + 0] = tf32f(v.x);
            Qs[rr * 68 + c4 + 1] = tf32f(v.y);
            Qs[rr * 68 + c4 + 2] = tf32f(v.z);
            Qs[rr * 68 + c4 + 3] = tf32f(v.w);
        }
    }

    float o[8][4];
#pragma unroll
    for (int ni = 0; ni < 8; ni++)
#pragma unroll
        for (int j = 0; j < 4; j++) o[ni][j] = 0.f;
    float m0 = -INFINITY, m1 = -INFINITY, l0 = 0.f, l1 = 0.f;

    __syncthreads();

    for (int t0 = 0; t0 < SS; t0 += 64) {
        // load K,V tiles (tf32)
        {
            int c4 = (tid & 15) * 4;
            int r = tid >> 4;
#pragma unroll
            for (int i = 0; i < 4; i++) {
                int rr = r + i * 16;
                float4 kv = *(const float4*)&Kg[(size_t)(t0 + rr) * DD + c4];
                Ks[rr * 68 + c4 + 0] = tf32f(kv.x);
                Ks[rr * 68 + c4 + 1] = tf32f(kv.y);
                Ks[rr * 68 + c4 + 2] = tf32f(kv.z);
                Ks[rr * 68 + c4 + 3] = tf32f(kv.w);
                float4 vv = *(const float4*)&Vg[(size_t)(t0 + rr) * MM + c4];
                Vs[rr * 72 + c4 + 0] = tf32f(vv.x);
                Vs[rr * 72 + c4 + 1] = tf32f(vv.y);
                Vs[rr * 72 + c4 + 2] = tf32f(vv.z);
                Vs[rr * 72 + c4 + 3] = tf32f(vv.w);
            }
        }
        __syncthreads();

        // S = Q @ K^T
        float s[8][4];
#pragma unroll
        for (int ni = 0; ni < 8; ni++)
#pragma unroll
            for (int j = 0; j < 4; j++) s[ni][j] = 0.f;

#pragma unroll
        for (int kc = 0; kc < 8; kc++) {
            const int k8 = kc * 8;
            unsigned a[4];
            a[0] = __float_as_uint(Qs[(wr + gr) * 68 + k8 + tc]);
            a[1] = __float_as_uint(Qs[(wr + gr + 8) * 68 + k8 + tc]);
            a[2] = __float_as_uint(Qs[(wr + gr) * 68 + k8 + tc + 4]);
            a[3] = __float_as_uint(Qs[(wr + gr + 8) * 68 + k8 + tc + 4]);
#pragma unroll
            for (int ni = 0; ni < 8; ni++) {
                unsigned b[2];
                b[0] = __float_as_uint(Ks[(ni * 8 + gr) * 68 + k8 + tc]);
                b[1] = __float_as_uint(Ks[(ni * 8 + gr) * 68 + k8 + tc + 4]);
                mma8(s[ni], a, b);
            }
        }

        // scale + mask
        const int r0g = q0 + wr + gr;
        const int r1g = r0g + 8;
#pragma unroll
        for (int ni = 0; ni < 8; ni++) {
            int cg = t0 + ni * 8 + 2 * tc;
            int2 mk0 = *(const int2*)&mask[(size_t)r0g * SS + cg];
            int2 mk1 = *(const int2*)&mask[(size_t)r1g * SS + cg];
            s[ni][0] = mk0.x ? s[ni][0] * 0.125f : -INFINITY;
            s[ni][1] = mk0.y ? s[ni][1] * 0.125f : -INFINITY;
            s[ni][2] = mk1.x ? s[ni][2] * 0.125f : -INFINITY;
            s[ni][3] = mk1.y ? s[ni][3] * 0.125f : -INFINITY;
        }

        // row max (reduce over n-frags then over the 4 lanes of the row group)
        float pm0 = -INFINITY, pm1 = -INFINITY;
#pragma unroll
        for (int ni = 0; ni < 8; ni++) {
            pm0 = fmaxf(pm0, fmaxf(s[ni][0], s[ni][1]));
            pm1 = fmaxf(pm1, fmaxf(s[ni][2], s[ni][3]));
        }
        pm0 = fmaxf(pm0, __shfl_xor_sync(0xffffffff, pm0, 1));
        pm0 = fmaxf(pm0, __shfl_xor_sync(0xffffffff, pm0, 2));
        pm1 = fmaxf(pm1, __shfl_xor_sync(0xffffffff, pm1, 1));
        pm1 = fmaxf(pm1, __shfl_xor_sync(0xffffffff, pm1, 2));
        float nm0 = fmaxf(m0, pm0), nm1 = fmaxf(m1, pm1);
        float al0 = (nm0 == -INFINITY) ? 1.f : __expf(m0 - nm0);
        float al1 = (nm1 == -INFINITY) ? 1.f : __expf(m1 - nm1);
        m0 = nm0; m1 = nm1;

        // p = exp(s - m), accumulate row sums, stash P (tf32) in warp-private smem
        float ps0 = 0.f, ps1 = 0.f;
#pragma unroll
        for (int ni = 0; ni < 8; ni++) {
            float p0 = (s[ni][0] == -INFINITY) ? 0.f : __expf(s[ni][0] - m0);
            float p1 = (s[ni][1] == -INFINITY) ? 0.f : __expf(s[ni][1] - m0);
            float p2 = (s[ni][2] == -INFINITY) ? 0.f : __expf(s[ni][2] - m1);
            float p3 = (s[ni][3] == -INFINITY) ? 0.f : __expf(s[ni][3] - m1);
            ps0 += p0 + p1;  ps1 += p2 + p3;
            int cl = ni * 8 + 2 * tc;
            float2 w0 = {tf32f(p0), tf32f(p1)};
            float2 w1 = {tf32f(p2), tf32f(p3)};
            *(float2*)&Ps[(wr + gr) * 68 + cl] = w0;
            *(float2*)&Ps[(wr + gr + 8) * 68 + cl] = w1;
        }
        ps0 += __shfl_xor_sync(0xffffffff, ps0, 1);
        ps0 += __shfl_xor_sync(0xffffffff, ps0, 2);
        ps1 += __shfl_xor_sync(0xffffffff, ps1, 1);
        ps1 += __shfl_xor_sync(0xffffffff, ps1, 2);
        l0 = l0 * al0 + ps0;
        l1 = l1 * al1 + ps1;

        // rescale O
#pragma unroll
        for (int ni = 0; ni < 8; ni++) {
            o[ni][0] *= al0; o[ni][1] *= al0;
            o[ni][2] *= al1; o[ni][3] *= al1;
        }
        __syncwarp();

        // O += P @ V
#pragma unroll
        for (int kc = 0; kc < 8; kc++) {
            const int k8 = kc * 8;
            unsigned a[4];
            a[0] = __float_as_uint(Ps[(wr + gr) * 68 + k8 + tc]);
            a[1] = __float_as_uint(Ps[(wr + gr + 8) * 68 + k8 + tc]);
            a[2] = __float_as_uint(Ps[(wr + gr) * 68 + k8 + tc + 4]);
            a[3] = __float_as_uint(Ps[(wr + gr + 8) * 68 + k8 + tc + 4]);
#pragma unroll
            for (int ni = 0; ni < 8; ni++) {
                unsigned b[2];
                b[0] = __float_as_uint(Vs[(k8 + tc) * 72 + ni * 8 + gr]);
                b[1] = __float_as_uint(Vs[(k8 + tc + 4) * 72 + ni * 8 + gr]);
                mma8(o[ni], a, b);
            }
        }
        __syncthreads();
    }

    // normalize + write concat layout
    float inv0 = (l0 > 0.f) ? 1.f / l0 : 0.f;
    float inv1 = (l1 > 0.f) ? 1.f / l1 : 0.f;
#pragma unroll
    for (int ni = 0; ni < 8; ni++) {
        int cl = h * MM + ni * 8 + 2 * tc;
        int r0 = q0 + wr + gr;
        float2 v0 = {o[ni][0] * inv0, o[ni][1] * inv0};
        float2 v1 = {o[ni][2] * inv1, o[ni][3] * inv1};
        *(float2*)&g_O[(size_t)r0 * (HH * MM) + cl] = v0;
        *(float2*)&g_O[(size_t)(r0 + 8) * (HH * MM) + cl] = v1;
    }
}

// ---------------------------------------------------------------------------
extern "C" void kernel_launch(void* const* d_in, const int* in_sizes, int n_in,
                              void* d_out, int out_size)
{
    const float* x    = (const float*)d_in[0];
    const float* z    = (const float*)d_in[1];
    const int*   mask = (const int*)  d_in[2];
    const float* Wq   = (const float*)d_in[3];
    const float* bq   = (const float*)d_in[4];
    const float* Wk   = (const float*)d_in[5];
    const float* bk   = (const float*)d_in[6];
    const float* Wv   = (const float*)d_in[7];
    const float* bv   = (const float*)d_in[8];
    const float* W0   = (const float*)d_in[9];
    const float* b0   = (const float*)d_in[10];
    float* out = (float*)d_out;

    static bool attr_set = false;
    if (!attr_set) {
        cudaFuncSetAttribute(qkv_kernel, cudaFuncAttributeMaxDynamicSharedMemorySize,
                             PROJ_SMEM_FLOATS * 4);
        cudaFuncSetAttribute(out_proj_kernel, cudaFuncAttributeMaxDynamicSharedMemorySize,
                             PROJ_SMEM_FLOATS * 4);
        cudaFuncSetAttribute(attn_kernel, cudaFuncAttributeMaxDynamicSharedMemorySize,
                             ATTN_SMEM_FLOATS * 4);
        attr_set = true;
    }

    qkv_kernel<<<dim3(SS/128, HH, 3), 256, PROJ_SMEM_FLOATS * 4>>>(
        x, z, Wq, bq, Wk, bk, Wv, bv);
    attn_kernel<<<dim3(SS/128, HH), 256, ATTN_SMEM_FLOATS * 4>>>(mask);
    out_proj_kernel<<<dim3(SS/128, OO/64), 256, PROJ_SMEM_FLOATS * 4>>>(W0, b0, out);
}

// round 3
// speedup vs baseline: 3.2965x; 1.3332x over previous
#include <cuda_runtime.h>
#include <cuda_bf16.h>
#include <math.h>

#define HH 16
#define EE 1024
#define DD 64
#define MM 64
#define OO 1024
#define SS 2048

__device__ float g_Q[HH * SS * DD];
__device__ float g_K[HH * SS * DD];
__device__ float g_V[HH * SS * MM];
__device__ float g_O[SS * HH * MM];

// ---------------------------------------------------------------------------
// helpers
// ---------------------------------------------------------------------------
__device__ __forceinline__ unsigned pack_bf2(__nv_bfloat16 a, __nv_bfloat16 b) {
    __nv_bfloat162 h;
    h.x = a; h.y = b;
    return *reinterpret_cast<unsigned*>(&h);
}
__device__ __forceinline__ void split_bf(float x, __nv_bfloat16& hi, __nv_bfloat16& lo) {
    hi = __float2bfloat16_rn(x);
    lo = __float2bfloat16_rn(x - __bfloat162float(hi));
}
__device__ __forceinline__ void mma16(float* d, const unsigned* a, const unsigned* b) {
    asm volatile(
        "mma.sync.aligned.m16n8k16.row.col.f32.bf16.bf16.f32 "
        "{%0,%1,%2,%3}, {%4,%5,%6,%7}, {%8,%9}, {%0,%1,%2,%3};"
        : "+f"(d[0]), "+f"(d[1]), "+f"(d[2]), "+f"(d[3])
        : "r"(a[0]), "r"(a[1]), "r"(a[2]), "r"(a[3]), "r"(b[0]), "r"(b[1]));
}

// ---------------------------------------------------------------------------
// Split-bf16 GEMM: C[128 x 64] tile of A[M,1024] @ B[1024,N] + bias.
// 256 threads, 8 warps, warp tile 32x32. 3 bf16 k16-MMAs per k16 chunk:
// hi*hi + hi*lo + lo*hi (~16-bit effective mantissa).
// ---------------------------------------------------------------------------
__device__ __forceinline__ void gemm_body(
    const float* __restrict__ A, int lda,
    const float* __restrict__ B, int ldb,
    const float* __restrict__ bias,
    float* __restrict__ C, int ldc,
    int row0, int col0)
{
    __shared__ __align__(16) __nv_bfloat16 Ah[128][40], Al[128][40];
    __shared__ __align__(16) unsigned B2h[16][72], B2l[16][72];  // packed k-pairs

    const int tid  = threadIdx.x;
    const int lane = tid & 31;
    const int warp = tid >> 5;
    const int gr = lane >> 2, tc = lane & 3;
    const int wm = (warp >> 1) * 32;
    const int wn = (warp & 1) * 32;

    float acc[2][4][4];
#pragma unroll
    for (int mi = 0; mi < 2; mi++)
#pragma unroll
        for (int ni = 0; ni < 4; ni++)
#pragma unroll
            for (int j = 0; j < 4; j++) acc[mi][ni][j] = 0.f;

    const int a_r  = tid >> 3;        // 0..31
    const int a_c4 = (tid & 7) * 4;   // 0..28
    const int b_pr = tid >> 4;        // 0..15 packed pair-row
    const int b_c4 = (tid & 15) * 4;  // 0..60

    for (int k0 = 0; k0 < 1024; k0 += 32) {
        // A tile 128x32 -> split hi/lo bf16
#pragma unroll
        for (int i = 0; i < 4; i++) {
            int r = a_r + i * 32;
            float4 v = *(const float4*)&A[(size_t)(row0 + r) * lda + k0 + a_c4];
            __nv_bfloat16 h, l;
            split_bf(v.x, h, l); Ah[r][a_c4 + 0] = h; Al[r][a_c4 + 0] = l;
            split_bf(v.y, h, l); Ah[r][a_c4 + 1] = h; Al[r][a_c4 + 1] = l;
            split_bf(v.z, h, l); Ah[r][a_c4 + 2] = h; Al[r][a_c4 + 2] = l;
            split_bf(v.w, h, l); Ah[r][a_c4 + 3] = h; Al[r][a_c4 + 3] = l;
        }
        // B tile 32x64 -> packed (k even, k odd) bf16 pairs per column
        {
            float4 v0 = *(const float4*)&B[(size_t)(k0 + 2 * b_pr) * ldb + col0 + b_c4];
            float4 v1 = *(const float4*)&B[(size_t)(k0 + 2 * b_pr + 1) * ldb + col0 + b_c4];
            __nv_bfloat16 h0, l0, h1, l1;
            split_bf(v0.x, h0, l0); split_bf(v1.x, h1, l1);
            B2h[b_pr][b_c4 + 0] = pack_bf2(h0, h1); B2l[b_pr][b_c4 + 0] = pack_bf2(l0, l1);
            split_bf(v0.y, h0, l0); split_bf(v1.y, h1, l1);
            B2h[b_pr][b_c4 + 1] = pack_bf2(h0, h1); B2l[b_pr][b_c4 + 1] = pack_bf2(l0, l1);
            split_bf(v0.z, h0, l0); split_bf(v1.z, h1, l1);
            B2h[b_pr][b_c4 + 2] = pack_bf2(h0, h1); B2l[b_pr][b_c4 + 2] = pack_bf2(l0, l1);
            split_bf(v0.w, h0, l0); split_bf(v1.w, h1, l1);
            B2h[b_pr][b_c4 + 3] = pack_bf2(h0, h1); B2l[b_pr][b_c4 + 3] = pack_bf2(l0, l1);
        }
        __syncthreads();

#pragma unroll
        for (int kc = 0; kc < 2; kc++) {
            const int k16 = kc * 16;
            const int kp  = kc * 8;
            unsigned ah[2][4], al[2][4];
#pragma unroll
            for (int mi = 0; mi < 2; mi++) {
                int rb = wm + mi * 16;
                ah[mi][0] = *(const unsigned*)&Ah[rb + gr][k16 + 2 * tc];
                ah[mi][1] = *(const unsigned*)&Ah[rb + gr + 8][k16 + 2 * tc];
                ah[mi][2] = *(const unsigned*)&Ah[rb + gr][k16 + 2 * tc + 8];
                ah[mi][3] = *(const unsigned*)&Ah[rb + gr + 8][k16 + 2 * tc + 8];
                al[mi][0] = *(const unsigned*)&Al[rb + gr][k16 + 2 * tc];
                al[mi][1] = *(const unsigned*)&Al[rb + gr + 8][k16 + 2 * tc];
                al[mi][2] = *(const unsigned*)&Al[rb + gr][k16 + 2 * tc + 8];
                al[mi][3] = *(const unsigned*)&Al[rb + gr + 8][k16 + 2 * tc + 8];
            }
            unsigned bh[4][2], bl[4][2];
#pragma unroll
            for (int ni = 0; ni < 4; ni++) {
                int cb = wn + ni * 8 + gr;
                bh[ni][0] = B2h[kp + tc][cb];
                bh[ni][1] = B2h[kp + tc + 4][cb];
                bl[ni][0] = B2l[kp + tc][cb];
                bl[ni][1] = B2l[kp + tc + 4][cb];
            }
#pragma unroll
            for (int mi = 0; mi < 2; mi++)
#pragma unroll
                for (int ni = 0; ni < 4; ni++) {
                    mma16(acc[mi][ni], ah[mi], bl[ni]);
                    mma16(acc[mi][ni], al[mi], bh[ni]);
                    mma16(acc[mi][ni], ah[mi], bh[ni]);
                }
        }
        __syncthreads();
    }

#pragma unroll
    for (int mi = 0; mi < 2; mi++)
#pragma unroll
        for (int ni = 0; ni < 4; ni++) {
            int cl = wn + ni * 8 + 2 * tc;
            int r0 = row0 + wm + mi * 16 + gr;
            float b0v = bias[cl], b1v = bias[cl + 1];
            float2 v0 = {acc[mi][ni][0] + b0v, acc[mi][ni][1] + b1v};
            float2 v1 = {acc[mi][ni][2] + b0v, acc[mi][ni][3] + b1v};
            *(float2*)&C[(size_t)r0 * ldc + col0 + cl] = v0;
            *(float2*)&C[(size_t)(r0 + 8) * ldc + col0 + cl] = v1;
        }
}

// ---------------------------------------------------------------------------
__global__ __launch_bounds__(256, 1) void qkv_kernel(
    const float* __restrict__ x, const float* __restrict__ z,
    const float* __restrict__ Wq, const float* __restrict__ bq,
    const float* __restrict__ Wk, const float* __restrict__ bk,
    const float* __restrict__ Wv, const float* __restrict__ bv)
{
    const int h = blockIdx.y, kind = blockIdx.z;
    const int row0 = blockIdx.x * 128;
    const float *A, *B, *bias;
    float* C;
    if (kind == 0) { A = x; B = Wq + (size_t)h*EE*DD; bias = bq + h*DD; C = g_Q + (size_t)h*SS*DD; }
    else if (kind == 1) { A = z; B = Wk + (size_t)h*EE*DD; bias = bk + h*DD; C = g_K + (size_t)h*SS*DD; }
    else { A = z; B = Wv + (size_t)h*EE*MM; bias = bv + h*MM; C = g_V + (size_t)h*SS*MM; }
    gemm_body(A, EE, B, DD, bias, C, DD, row0, 0);
}

__global__ __launch_bounds__(256, 1) void out_proj_kernel(
    const float* __restrict__ W0, const float* __restrict__ b0,
    float* __restrict__ out)
{
    gemm_body(g_O, HH*MM, W0, OO, b0 + blockIdx.y * 64, out, OO,
              blockIdx.x * 128, blockIdx.y * 64);
}

// ---------------------------------------------------------------------------
// Flash attention, split-bf16 MMA, register-direct P.
// grid = (S/128, H), 256 threads. Warp w owns query rows [w*16, w*16+16).
// smem (dynamic, 73728 B):
//   Qh[128][72] Ql[128][72] (bf16)      36864
//   Kh[64][72]  Kl[64][72]  (bf16)      18432
//   V2h[32][72] V2l[32][72] (packed u32) 18432
// ---------------------------------------------------------------------------
#define ATTN_SMEM_BYTES (128*72*2*2 + 64*72*2*2 + 32*72*4*2)

__global__ __launch_bounds__(256, 1) void attn_kernel(const int* __restrict__ mask)
{
    extern __shared__ char smraw[];
    __nv_bfloat16 (*Qh)[72] = (__nv_bfloat16(*)[72])(smraw);
    __nv_bfloat16 (*Ql)[72] = (__nv_bfloat16(*)[72])(smraw + 128*72*2);
    __nv_bfloat16 (*Kh)[72] = (__nv_bfloat16(*)[72])(smraw + 2*128*72*2);
    __nv_bfloat16 (*Kl)[72] = (__nv_bfloat16(*)[72])(smraw + 2*128*72*2 + 64*72*2);
    unsigned (*V2h)[72] = (unsigned(*)[72])(smraw + 2*128*72*2 + 2*64*72*2);
    unsigned (*V2l)[72] = (unsigned(*)[72])(smraw + 2*128*72*2 + 2*64*72*2 + 32*72*4);

    const int h  = blockIdx.y;
    const int q0 = blockIdx.x * 128;
    const int tid  = threadIdx.x;
    const int lane = tid & 31;
    const int warp = tid >> 5;
    const int gr = lane >> 2, tc = lane & 3;
    const int wr = warp * 16;

    const float* Qg = g_Q + (size_t)h * SS * DD;
    const float* Kg = g_K + (size_t)h * SS * DD;
    const float* Vg = g_V + (size_t)h * SS * MM;

    // load Q tile (split bf16)
    {
        int c4 = (tid & 15) * 4;
        int r = tid >> 4;
#pragma unroll
        for (int i = 0; i < 8; i++) {
            int rr = r + i * 16;
            float4 v = *(const float4*)&Qg[(size_t)(q0 + rr) * DD + c4];
            __nv_bfloat16 hh, ll;
            split_bf(v.x, hh, ll); Qh[rr][c4 + 0] = hh; Ql[rr][c4 + 0] = ll;
            split_bf(v.y, hh, ll); Qh[rr][c4 + 1] = hh; Ql[rr][c4 + 1] = ll;
            split_bf(v.z, hh, ll); Qh[rr][c4 + 2] = hh; Ql[rr][c4 + 2] = ll;
            split_bf(v.w, hh, ll); Qh[rr][c4 + 3] = hh; Ql[rr][c4 + 3] = ll;
        }
    }

    float o[8][4];
#pragma unroll
    for (int ni = 0; ni < 8; ni++)
#pragma unroll
        for (int j = 0; j < 4; j++) o[ni][j] = 0.f;
    float m0 = -1e30f, m1 = -1e30f, l0 = 0.f, l1 = 0.f;

    __syncthreads();

    for (int t0 = 0; t0 < SS; t0 += 64) {
        // K tile (split bf16, row-major)
        {
            int c4 = (tid & 15) * 4;
            int r = tid >> 4;
#pragma unroll
            for (int i = 0; i < 4; i++) {
                int rr = r + i * 16;
                float4 kv = *(const float4*)&Kg[(size_t)(t0 + rr) * DD + c4];
                __nv_bfloat16 hh, ll;
                split_bf(kv.x, hh, ll); Kh[rr][c4 + 0] = hh; Kl[rr][c4 + 0] = ll;
                split_bf(kv.y, hh, ll); Kh[rr][c4 + 1] = hh; Kl[rr][c4 + 1] = ll;
                split_bf(kv.z, hh, ll); Kh[rr][c4 + 2] = hh; Kl[rr][c4 + 2] = ll;
                split_bf(kv.w, hh, ll); Kh[rr][c4 + 3] = hh; Kl[rr][c4 + 3] = ll;
            }
        }
        // V tile (packed t-pairs per column)
        {
            int vp = tid >> 3;            // 0..31 (covers t = 2vp, 2vp+1)
            int c8 = (tid & 7) * 8;
            float4 u0 = *(const float4*)&Vg[(size_t)(t0 + 2*vp) * MM + c8];
            float4 u1 = *(const float4*)&Vg[(size_t)(t0 + 2*vp) * MM + c8 + 4];
            float4 w0 = *(const float4*)&Vg[(size_t)(t0 + 2*vp + 1) * MM + c8];
            float4 w1 = *(const float4*)&Vg[(size_t)(t0 + 2*vp + 1) * MM + c8 + 4];
            const float* ua = (const float*)&u0;
            const float* ub = (const float*)&u1;
            const float* wa = (const float*)&w0;
            const float* wb = (const float*)&w1;
#pragma unroll
            for (int j = 0; j < 4; j++) {
                __nv_bfloat16 h0, lo0, h1, lo1;
                split_bf(ua[j], h0, lo0); split_bf(wa[j], h1, lo1);
                V2h[vp][c8 + j] = pack_bf2(h0, h1);
                V2l[vp][c8 + j] = pack_bf2(lo0, lo1);
                split_bf(ub[j], h0, lo0); split_bf(wb[j], h1, lo1);
                V2h[vp][c8 + 4 + j] = pack_bf2(h0, h1);
                V2l[vp][c8 + 4 + j] = pack_bf2(lo0, lo1);
            }
        }
        __syncthreads();

        // S = Q @ K^T (split bf16)
        float s[8][4];
#pragma unroll
        for (int ni = 0; ni < 8; ni++)
#pragma unroll
            for (int j = 0; j < 4; j++) s[ni][j] = 0.f;

#pragma unroll
        for (int kc = 0; kc < 4; kc++) {
            const int k16 = kc * 16;
            unsigned qh[4], ql[4];
            qh[0] = *(const unsigned*)&Qh[wr + gr][k16 + 2*tc];
            qh[1] = *(const unsigned*)&Qh[wr + gr + 8][k16 + 2*tc];
            qh[2] = *(const unsigned*)&Qh[wr + gr][k16 + 2*tc + 8];
            qh[3] = *(const unsigned*)&Qh[wr + gr + 8][k16 + 2*tc + 8];
            ql[0] = *(const unsigned*)&Ql[wr + gr][k16 + 2*tc];
            ql[1] = *(const unsigned*)&Ql[wr + gr + 8][k16 + 2*tc];
            ql[2] = *(const unsigned*)&Ql[wr + gr][k16 + 2*tc + 8];
            ql[3] = *(const unsigned*)&Ql[wr + gr + 8][k16 + 2*tc + 8];
#pragma unroll
            for (int ni = 0; ni < 8; ni++) {
                int t = ni * 8 + gr;
                unsigned kh[2], kl[2];
                kh[0] = *(const unsigned*)&Kh[t][k16 + 2*tc];
                kh[1] = *(const unsigned*)&Kh[t][k16 + 2*tc + 8];
                kl[0] = *(const unsigned*)&Kl[t][k16 + 2*tc];
                kl[1] = *(const unsigned*)&Kl[t][k16 + 2*tc + 8];
                mma16(s[ni], qh, kl);
                mma16(s[ni], ql, kh);
                mma16(s[ni], qh, kh);
            }
        }

        // scale + additive mask
        const int r0g = q0 + wr + gr;
        const int r1g = r0g + 8;
#pragma unroll
        for (int ni = 0; ni < 8; ni++) {
            int cg = t0 + ni * 8 + 2 * tc;
            int2 mk0 = *(const int2*)&mask[(size_t)r0g * SS + cg];
            int2 mk1 = *(const int2*)&mask[(size_t)r1g * SS + cg];
            s[ni][0] = s[ni][0] * 0.125f + (mk0.x ? 0.f : -1e30f);
            s[ni][1] = s[ni][1] * 0.125f + (mk0.y ? 0.f : -1e30f);
            s[ni][2] = s[ni][2] * 0.125f + (mk1.x ? 0.f : -1e30f);
            s[ni][3] = s[ni][3] * 0.125f + (mk1.y ? 0.f : -1e30f);
        }

        // row max
        float pm0 = -1e30f, pm1 = -1e30f;
#pragma unroll
        for (int ni = 0; ni < 8; ni++) {
            pm0 = fmaxf(pm0, fmaxf(s[ni][0], s[ni][1]));
            pm1 = fmaxf(pm1, fmaxf(s[ni][2], s[ni][3]));
        }
        pm0 = fmaxf(pm0, __shfl_xor_sync(0xffffffff, pm0, 1));
        pm0 = fmaxf(pm0, __shfl_xor_sync(0xffffffff, pm0, 2));
        pm1 = fmaxf(pm1, __shfl_xor_sync(0xffffffff, pm1, 1));
        pm1 = fmaxf(pm1, __shfl_xor_sync(0xffffffff, pm1, 2));
        float nm0 = fmaxf(m0, pm0), nm1 = fmaxf(m1, pm1);
        float al0 = __expf(m0 - nm0);
        float al1 = __expf(m1 - nm1);
        m0 = nm0; m1 = nm1;

        // p = exp(s - m): pack split-bf16 A-fragments directly in registers
        unsigned ph01[8], ph23[8], pl01[8], pl23[8];
        float ps0 = 0.f, ps1 = 0.f;
#pragma unroll
        for (int ni = 0; ni < 8; ni++) {
            float p0 = __expf(s[ni][0] - m0);
            float p1 = __expf(s[ni][1] - m0);
            float p2 = __expf(s[ni][2] - m1);
            float p3 = __expf(s[ni][3] - m1);
            ps0 += p0 + p1;  ps1 += p2 + p3;
            __nv_bfloat16 h0, lo0, h1, lo1;
            split_bf(p0, h0, lo0); split_bf(p1, h1, lo1);
            ph01[ni] = pack_bf2(h0, h1); pl01[ni] = pack_bf2(lo0, lo1);
            split_bf(p2, h0, lo0); split_bf(p3, h1, lo1);
            ph23[ni] = pack_bf2(h0, h1); pl23[ni] = pack_bf2(lo0, lo1);
        }
        ps0 += __shfl_xor_sync(0xffffffff, ps0, 1);
        ps0 += __shfl_xor_sync(0xffffffff, ps0, 2);
        ps1 += __shfl_xor_sync(0xffffffff, ps1, 1);
        ps1 += __shfl_xor_sync(0xffffffff, ps1, 2);
        l0 = l0 * al0 + ps0;
        l1 = l1 * al1 + ps1;

        // rescale O, then O += P @ V (split bf16, A from registers)
#pragma unroll
        for (int ni = 0; ni < 8; ni++) {
            o[ni][0] *= al0; o[ni][1] *= al0;
            o[ni][2] *= al1; o[ni][3] *= al1;
        }
#pragma unroll
        for (int kc = 0; kc < 4; kc++) {
            unsigned a_h[4] = {ph01[2*kc], ph23[2*kc], ph01[2*kc+1], ph23[2*kc+1]};
            unsigned a_l[4] = {pl01[2*kc], pl23[2*kc], pl01[2*kc+1], pl23[2*kc+1]};
#pragma unroll
            for (int ni = 0; ni < 8; ni++) {
                int cb = ni * 8 + gr;
                unsigned vh[2], vl[2];
                vh[0] = V2h[kc*8 + tc][cb];
                vh[1] = V2h[kc*8 + tc + 4][cb];
                vl[0] = V2l[kc*8 + tc][cb];
                vl[1] = V2l[kc*8 + tc + 4][cb];
                mma16(o[ni], a_h, vl);
                mma16(o[ni], a_l, vh);
                mma16(o[ni], a_h, vh);
            }
        }
        __syncthreads();
    }

    // normalize + write concat layout
    float inv0 = (l0 > 0.f) ? 1.f / l0 : 0.f;
    float inv1 = (l1 > 0.f) ? 1.f / l1 : 0.f;
#pragma unroll
    for (int ni = 0; ni < 8; ni++) {
        int cl = h * MM + ni * 8 + 2 * tc;
        int r0 = q0 + wr + gr;
        float2 v0 = {o[ni][0] * inv0, o[ni][1] * inv0};
        float2 v1 = {o[ni][2] * inv1, o[ni][3] * inv1};
        *(float2*)&g_O[(size_t)r0 * (HH * MM) + cl] = v0;
        *(float2*)&g_O[(size_t)(r0 + 8) * (HH * MM) + cl] = v1;
    }
}

// ---------------------------------------------------------------------------
extern "C" void kernel_launch(void* const* d_in, const int* in_sizes, int n_in,
                              void* d_out, int out_size)
{
    const float* x    = (const float*)d_in[0];
    const float* z    = (const float*)d_in[1];
    const int*   mask = (const int*)  d_in[2];
    const float* Wq   = (const float*)d_in[3];
    const float* bq   = (const float*)d_in[4];
    const float* Wk   = (const float*)d_in[5];
    const float* bk   = (const float*)d_in[6];
    const float* Wv   = (const float*)d_in[7];
    const float* bv   = (const float*)d_in[8];
    const float* W0   = (const float*)d_in[9];
    const float* b0   = (const float*)d_in[10];
    float* out = (float*)d_out;

    static bool attr_set = false;
    if (!attr_set) {
        cudaFuncSetAttribute(attn_kernel, cudaFuncAttributeMaxDynamicSharedMemorySize,
                             ATTN_SMEM_BYTES);
        attr_set = true;
    }

    qkv_kernel<<<dim3(SS/128, HH, 3), 256>>>(x, z, Wq, bq, Wk, bk, Wv, bv);
    attn_kernel<<<dim3(SS/128, HH), 256, ATTN_SMEM_BYTES>>>(mask);
    out_proj_kernel<<<dim3(SS/128, OO/64), 256>>>(W0, b0, out);
}

// round 4
// speedup vs baseline: 3.8750x; 1.1755x over previous
#include <cuda_runtime.h>
#include <cuda_bf16.h>
#include <cuda_fp16.h>
#include <math.h>

#define HH 16
#define EE 1024
#define DD 64
#define MM 64
#define OO 1024
#define SS 2048

// ---------------------------------------------------------------------------
// Device-global scratch (allocation-free)
// ---------------------------------------------------------------------------
__device__ __align__(16) __nv_bfloat16 g_xh[SS * EE], g_xl[SS * EE];
__device__ __align__(16) __nv_bfloat16 g_zh[SS * EE], g_zl[SS * EE];
__device__ __align__(16) unsigned g_Wh[3 * HH * (EE / 2) * DD];   // packed k-pairs
__device__ __align__(16) unsigned g_Wl[3 * HH * (EE / 2) * DD];
__device__ __align__(16) unsigned g_W0h[(HH * MM / 2) * OO];
__device__ __align__(16) unsigned g_W0l[(HH * MM / 2) * OO];
__device__ __align__(16) __half g_Q16[HH * SS * DD];
__device__ __align__(16) __half g_K16[HH * SS * DD];
__device__ __align__(16) __half g_V16[HH * SS * MM];
__device__ __align__(16) __nv_bfloat16 g_Oh[SS * HH * MM], g_Ol[SS * HH * MM];

// ---------------------------------------------------------------------------
// helpers
// ---------------------------------------------------------------------------
__device__ __forceinline__ unsigned pack_bf2(__nv_bfloat16 a, __nv_bfloat16 b) {
    __nv_bfloat162 h; h.x = a; h.y = b;
    return *reinterpret_cast<unsigned*>(&h);
}
__device__ __forceinline__ void split_bf(float x, __nv_bfloat16& hi, __nv_bfloat16& lo) {
    hi = __float2bfloat16_rn(x);
    lo = __float2bfloat16_rn(x - __bfloat162float(hi));
}
__device__ __forceinline__ void mma_bf16(float* d, const unsigned* a, const unsigned* b) {
    asm volatile(
        "mma.sync.aligned.m16n8k16.row.col.f32.bf16.bf16.f32 "
        "{%0,%1,%2,%3}, {%4,%5,%6,%7}, {%8,%9}, {%0,%1,%2,%3};"
        : "+f"(d[0]), "+f"(d[1]), "+f"(d[2]), "+f"(d[3])
        : "r"(a[0]), "r"(a[1]), "r"(a[2]), "r"(a[3]), "r"(b[0]), "r"(b[1]));
}
__device__ __forceinline__ void mma_f16(float* d, const unsigned* a, const unsigned* b) {
    asm volatile(
        "mma.sync.aligned.m16n8k16.row.col.f32.f16.f16.f32 "
        "{%0,%1,%2,%3}, {%4,%5,%6,%7}, {%8,%9}, {%0,%1,%2,%3};"
        : "+f"(d[0]), "+f"(d[1]), "+f"(d[2]), "+f"(d[3])
        : "r"(a[0]), "r"(a[1]), "r"(a[2]), "r"(a[3]), "r"(b[0]), "r"(b[1]));
}

// ---------------------------------------------------------------------------
// Prepass kernels
// ---------------------------------------------------------------------------
__global__ void split_xz_kernel(const float* __restrict__ x, const float* __restrict__ z)
{
    int i = (blockIdx.x * 256 + threadIdx.x) * 4;
    float4 vx = *(const float4*)&x[i];
    float4 vz = *(const float4*)&z[i];
    const float* px = (const float*)&vx;
    const float* pz = (const float*)&vz;
#pragma unroll
    for (int j = 0; j < 4; j++) {
        __nv_bfloat16 h, l;
        split_bf(px[j], h, l); g_xh[i + j] = h; g_xl[i + j] = l;
        split_bf(pz[j], h, l); g_zh[i + j] = h; g_zl[i + j] = l;
    }
}

__global__ void pack_w_kernel(const float* __restrict__ Wq,
                              const float* __restrict__ Wk,
                              const float* __restrict__ Wv)
{
    int i = blockIdx.x * 256 + threadIdx.x;      // over 3*16*512*64
    int d = i & 63;
    int p = (i >> 6) & 511;
    int h = (i >> 15) & 15;
    int kind = i >> 19;
    const float* W = (kind == 0) ? Wq : (kind == 1) ? Wk : Wv;
    const float* src = W + ((size_t)h * EE + 2 * p) * DD + d;
    float a = src[0], b = src[DD];
    __nv_bfloat16 ha, la, hb, lb;
    split_bf(a, ha, la); split_bf(b, hb, lb);
    g_Wh[i] = pack_bf2(ha, hb);
    g_Wl[i] = pack_bf2(la, lb);
}

__global__ void pack_w0_kernel(const float* __restrict__ W0)
{
    int i = blockIdx.x * 256 + threadIdx.x;      // over 512*1024
    int o = i & 1023;
    int p = i >> 10;
    const float* src = W0 + (size_t)(2 * p) * OO + o;
    float a = src[0], b = src[OO];
    __nv_bfloat16 ha, la, hb, lb;
    split_bf(a, ha, la); split_bf(b, hb, lb);
    g_W0h[i] = pack_bf2(ha, hb);
    g_W0l[i] = pack_bf2(la, lb);
}

// ---------------------------------------------------------------------------
// Split-bf16 GEMM core: acc[2][4][4] = A[128,1024] @ B[1024,64-tile]
// All inputs pre-split/pre-packed. BK = 64. 256 threads, 8 warps (32x32 tiles).
// smem: Ah/Al [128][72] bf16, B2h/B2l [32][72] u32  -> 55296 bytes dynamic
// ---------------------------------------------------------------------------
#define PROJ_SMEM_BYTES (2 * 128 * 72 * 2 + 2 * 32 * 72 * 4)

__device__ __forceinline__ void gemm_core(
    const __nv_bfloat16* __restrict__ Ah_g, const __nv_bfloat16* __restrict__ Al_g,
    const unsigned* __restrict__ Bh_g, const unsigned* __restrict__ Bl_g, int ldb,
    int row0, int bcol0, float acc[2][4][4], char* smraw)
{
    __nv_bfloat16 (*Ah)[72] = (__nv_bfloat16(*)[72])(smraw);
    __nv_bfloat16 (*Al)[72] = (__nv_bfloat16(*)[72])(smraw + 128 * 72 * 2);
    unsigned (*B2h)[72] = (unsigned(*)[72])(smraw + 2 * 128 * 72 * 2);
    unsigned (*B2l)[72] = (unsigned(*)[72])(smraw + 2 * 128 * 72 * 2 + 32 * 72 * 4);

    const int tid  = threadIdx.x;
    const int lane = tid & 31;
    const int warp = tid >> 5;
    const int gr = lane >> 2, tc = lane & 3;
    const int wm = (warp >> 1) * 32;
    const int wn = (warp & 1) * 32;

    const int a_r  = tid >> 1;
    const int a_s  = (tid & 1) * 32;
    const int b_r  = tid >> 3;
    const int b_c  = (tid & 7) * 8;

#pragma unroll
    for (int mi = 0; mi < 2; mi++)
#pragma unroll
        for (int ni = 0; ni < 4; ni++)
#pragma unroll
            for (int j = 0; j < 4; j++) acc[mi][ni][j] = 0.f;

    for (int k0 = 0; k0 < EE; k0 += 64) {
        // A tiles: direct 16B copies (no conversion)
        {
            const float4* sh = (const float4*)(Ah_g + (size_t)(row0 + a_r) * EE + k0 + a_s);
            const float4* sl = (const float4*)(Al_g + (size_t)(row0 + a_r) * EE + k0 + a_s);
            float4* dh = (float4*)&Ah[a_r][a_s];
            float4* dl = (float4*)&Al[a_r][a_s];
#pragma unroll
            for (int j = 0; j < 4; j++) { dh[j] = sh[j]; dl[j] = sl[j]; }
        }
        // B tiles (packed pairs)
        {
            const float4* sh = (const float4*)(Bh_g + (size_t)(k0 / 2 + b_r) * ldb + bcol0 + b_c);
            const float4* sl = (const float4*)(Bl_g + (size_t)(k0 / 2 + b_r) * ldb + bcol0 + b_c);
            float4* dh = (float4*)&B2h[b_r][b_c];
            float4* dl = (float4*)&B2l[b_r][b_c];
            dh[0] = sh[0]; dh[1] = sh[1];
            dl[0] = sl[0]; dl[1] = sl[1];
        }
        __syncthreads();

#pragma unroll
        for (int kc = 0; kc < 4; kc++) {
            const int k16 = kc * 16;
            const int kp  = kc * 8;
            unsigned ah[2][4], al[2][4];
#pragma unroll
            for (int mi = 0; mi < 2; mi++) {
                int rb = wm + mi * 16;
                ah[mi][0] = *(const unsigned*)&Ah[rb + gr][k16 + 2 * tc];
                ah[mi][1] = *(const unsigned*)&Ah[rb + gr + 8][k16 + 2 * tc];
                ah[mi][2] = *(const unsigned*)&Ah[rb + gr][k16 + 2 * tc + 8];
                ah[mi][3] = *(const unsigned*)&Ah[rb + gr + 8][k16 + 2 * tc + 8];
                al[mi][0] = *(const unsigned*)&Al[rb + gr][k16 + 2 * tc];
                al[mi][1] = *(const unsigned*)&Al[rb + gr + 8][k16 + 2 * tc];
                al[mi][2] = *(const unsigned*)&Al[rb + gr][k16 + 2 * tc + 8];
                al[mi][3] = *(const unsigned*)&Al[rb + gr + 8][k16 + 2 * tc + 8];
            }
            unsigned bh[4][2], bl[4][2];
#pragma unroll
            for (int ni = 0; ni < 4; ni++) {
                int cb = wn + ni * 8 + gr;
                bh[ni][0] = B2h[kp + tc][cb];
                bh[ni][1] = B2h[kp + tc + 4][cb];
                bl[ni][0] = B2l[kp + tc][cb];
                bl[ni][1] = B2l[kp + tc + 4][cb];
            }
#pragma unroll
            for (int mi = 0; mi < 2; mi++)
#pragma unroll
                for (int ni = 0; ni < 4; ni++) {
                    mma_bf16(acc[mi][ni], ah[mi], bl[ni]);
                    mma_bf16(acc[mi][ni], al[mi], bh[ni]);
                    mma_bf16(acc[mi][ni], ah[mi], bh[ni]);
                }
        }
        __syncthreads();
    }
}

// ---------------------------------------------------------------------------
// QKV: grid (16, H, 3). Writes fp16 Q/K/V.
// ---------------------------------------------------------------------------
__global__ __launch_bounds__(256) void qkv_kernel(
    const float* __restrict__ bq, const float* __restrict__ bk,
    const float* __restrict__ bv)
{
    extern __shared__ char smraw[];
    const int h = blockIdx.y, kind = blockIdx.z;
    const int row0 = blockIdx.x * 128;

    const __nv_bfloat16* Ah_g = (kind == 0) ? g_xh : g_zh;
    const __nv_bfloat16* Al_g = (kind == 0) ? g_xl : g_zl;
    const unsigned* Bh_g = g_Wh + (size_t)(kind * HH + h) * (512 * 64);
    const unsigned* Bl_g = g_Wl + (size_t)(kind * HH + h) * (512 * 64);
    const float* bias = ((kind == 0) ? bq : (kind == 1) ? bk : bv) + h * 64;
    __half* C = ((kind == 0) ? g_Q16 : (kind == 1) ? g_K16 : g_V16) + (size_t)h * SS * 64;

    float acc[2][4][4];
    gemm_core(Ah_g, Al_g, Bh_g, Bl_g, 64, row0, 0, acc, smraw);

    const int lane = threadIdx.x & 31;
    const int warp = threadIdx.x >> 5;
    const int gr = lane >> 2, tc = lane & 3;
    const int wm = (warp >> 1) * 32, wn = (warp & 1) * 32;
#pragma unroll
    for (int mi = 0; mi < 2; mi++)
#pragma unroll
        for (int ni = 0; ni < 4; ni++) {
            int cl = wn + ni * 8 + 2 * tc;
            int r0 = row0 + wm + mi * 16 + gr;
            float b0v = bias[cl], b1v = bias[cl + 1];
            *(__half2*)&C[(size_t)r0 * 64 + cl] =
                __floats2half2_rn(acc[mi][ni][0] + b0v, acc[mi][ni][1] + b1v);
            *(__half2*)&C[(size_t)(r0 + 8) * 64 + cl] =
                __floats2half2_rn(acc[mi][ni][2] + b0v, acc[mi][ni][3] + b1v);
        }
}

// ---------------------------------------------------------------------------
// Output projection: grid (16, 16). A = attn output (pre-split bf16).
// ---------------------------------------------------------------------------
__global__ __launch_bounds__(256) void out_proj_kernel(
    const float* __restrict__ b0, float* __restrict__ out)
{
    extern __shared__ char smraw[];
    const int row0 = blockIdx.x * 128;
    const int col0 = blockIdx.y * 64;

    float acc[2][4][4];
    gemm_core(g_Oh, g_Ol, g_W0h, g_W0l, OO, row0, col0, acc, smraw);

    const int lane = threadIdx.x & 31;
    const int warp = threadIdx.x >> 5;
    const int gr = lane >> 2, tc = lane & 3;
    const int wm = (warp >> 1) * 32, wn = (warp & 1) * 32;
#pragma unroll
    for (int mi = 0; mi < 2; mi++)
#pragma unroll
        for (int ni = 0; ni < 4; ni++) {
            int cl = wn + ni * 8 + 2 * tc;
            int r0 = row0 + wm + mi * 16 + gr;
            float b0v = b0[col0 + cl], b1v = b0[col0 + cl + 1];
            float2 v0 = {acc[mi][ni][0] + b0v, acc[mi][ni][1] + b1v};
            float2 v1 = {acc[mi][ni][2] + b0v, acc[mi][ni][3] + b1v};
            *(float2*)&out[(size_t)r0 * OO + col0 + cl] = v0;
            *(float2*)&out[(size_t)(r0 + 8) * OO + col0 + cl] = v1;
        }
}

// ---------------------------------------------------------------------------
// Flash attention, single-pass fp16 MMA, register-direct P.
// grid (S/128, H), 256 threads. smem 36864 B:
//   Qs half[128][72], Ks half[64][72], V2 u32[32][72] (t-pair packed half2)
// ---------------------------------------------------------------------------
#define ATTN_SMEM_BYTES (128 * 72 * 2 + 64 * 72 * 2 + 32 * 72 * 4)

__global__ __launch_bounds__(256) void attn_kernel(const int* __restrict__ mask)
{
    extern __shared__ char smraw[];
    __half (*Qs)[72] = (__half(*)[72])(smraw);
    __half (*Ks)[72] = (__half(*)[72])(smraw + 128 * 72 * 2);
    unsigned (*V2)[72] = (unsigned(*)[72])(smraw + 128 * 72 * 2 + 64 * 72 * 2);

    const int h  = blockIdx.y;
    const int q0 = blockIdx.x * 128;
    const int tid  = threadIdx.x;
    const int lane = tid & 31;
    const int warp = tid >> 5;
    const int gr = lane >> 2, tc = lane & 3;
    const int wr = warp * 16;

    const __half* Qg = g_Q16 + (size_t)h * SS * 64;
    const __half* Kg = g_K16 + (size_t)h * SS * 64;
    const __half* Vg = g_V16 + (size_t)h * SS * 64;

    // Q tile: direct copy
    {
        int r = tid >> 1, s = (tid & 1) * 32;
        const float4* src = (const float4*)(Qg + (size_t)(q0 + r) * 64 + s);
        float4* dst = (float4*)&Qs[r][s];
#pragma unroll
        for (int j = 0; j < 4; j++) dst[j] = src[j];
    }

    float o[8][4];
#pragma unroll
    for (int ni = 0; ni < 8; ni++)
#pragma unroll
        for (int j = 0; j < 4; j++) o[ni][j] = 0.f;
    float m0 = -1e30f, m1 = -1e30f, l0 = 0.f, l1 = 0.f;

    __syncthreads();

    for (int t0 = 0; t0 < SS; t0 += 64) {
        // K tile
        {
            int r = tid >> 2, s = (tid & 3) * 16;
            const float4* src = (const float4*)(Kg + (size_t)(t0 + r) * 64 + s);
            float4* dst = (float4*)&Ks[r][s];
            dst[0] = src[0]; dst[1] = src[1];
        }
        // V tile: pack (t even, t odd) half2 per column
        {
            int vp = tid >> 3, c8 = (tid & 7) * 8;
            uint4 u0 = *(const uint4*)(Vg + (size_t)(t0 + 2 * vp) * 64 + c8);
            uint4 u1 = *(const uint4*)(Vg + (size_t)(t0 + 2 * vp + 1) * 64 + c8);
            const unsigned* a = (const unsigned*)&u0;
            const unsigned* b = (const unsigned*)&u1;
#pragma unroll
            for (int j = 0; j < 4; j++) {
                V2[vp][c8 + 2 * j]     = __byte_perm(a[j], b[j], 0x5410);
                V2[vp][c8 + 2 * j + 1] = __byte_perm(a[j], b[j], 0x7632);
            }
        }
        __syncthreads();

        // S = Q @ K^T  (fp16, single pass)
        float s[8][4];
#pragma unroll
        for (int ni = 0; ni < 8; ni++)
#pragma unroll
            for (int j = 0; j < 4; j++) s[ni][j] = 0.f;

#pragma unroll
        for (int kc = 0; kc < 4; kc++) {
            const int k16 = kc * 16;
            unsigned a[4];
            a[0] = *(const unsigned*)&Qs[wr + gr][k16 + 2 * tc];
            a[1] = *(const unsigned*)&Qs[wr + gr + 8][k16 + 2 * tc];
            a[2] = *(const unsigned*)&Qs[wr + gr][k16 + 2 * tc + 8];
            a[3] = *(const unsigned*)&Qs[wr + gr + 8][k16 + 2 * tc + 8];
#pragma unroll
            for (int ni = 0; ni < 8; ni++) {
                unsigned b[2];
                b[0] = *(const unsigned*)&Ks[ni * 8 + gr][k16 + 2 * tc];
                b[1] = *(const unsigned*)&Ks[ni * 8 + gr][k16 + 2 * tc + 8];
                mma_f16(s[ni], a, b);
            }
        }

        // scale + additive mask
        const int r0g = q0 + wr + gr;
        const int r1g = r0g + 8;
#pragma unroll
        for (int ni = 0; ni < 8; ni++) {
            int cg = t0 + ni * 8 + 2 * tc;
            int2 mk0 = *(const int2*)&mask[(size_t)r0g * SS + cg];
            int2 mk1 = *(const int2*)&mask[(size_t)r1g * SS + cg];
            s[ni][0] = s[ni][0] * 0.125f + (mk0.x ? 0.f : -1e30f);
            s[ni][1] = s[ni][1] * 0.125f + (mk0.y ? 0.f : -1e30f);
            s[ni][2] = s[ni][2] * 0.125f + (mk1.x ? 0.f : -1e30f);
            s[ni][3] = s[ni][3] * 0.125f + (mk1.y ? 0.f : -1e30f);
        }

        // online softmax
        float pm0 = -1e30f, pm1 = -1e30f;
#pragma unroll
        for (int ni = 0; ni < 8; ni++) {
            pm0 = fmaxf(pm0, fmaxf(s[ni][0], s[ni][1]));
            pm1 = fmaxf(pm1, fmaxf(s[ni][2], s[ni][3]));
        }
        pm0 = fmaxf(pm0, __shfl_xor_sync(0xffffffff, pm0, 1));
        pm0 = fmaxf(pm0, __shfl_xor_sync(0xffffffff, pm0, 2));
        pm1 = fmaxf(pm1, __shfl_xor_sync(0xffffffff, pm1, 1));
        pm1 = fmaxf(pm1, __shfl_xor_sync(0xffffffff, pm1, 2));
        float nm0 = fmaxf(m0, pm0), nm1 = fmaxf(m1, pm1);
        float al0 = __expf(m0 - nm0);
        float al1 = __expf(m1 - nm1);
        m0 = nm0; m1 = nm1;

        // P in registers as fp16 A-fragments
        unsigned ph01[8], ph23[8];
        float ps0 = 0.f, ps1 = 0.f;
#pragma unroll
        for (int ni = 0; ni < 8; ni++) {
            float p0 = __expf(s[ni][0] - m0);
            float p1 = __expf(s[ni][1] - m0);
            float p2 = __expf(s[ni][2] - m1);
            float p3 = __expf(s[ni][3] - m1);
            ps0 += p0 + p1;  ps1 += p2 + p3;
            __half2 h01 = __floats2half2_rn(p0, p1);
            __half2 h23 = __floats2half2_rn(p2, p3);
            ph01[ni] = *(unsigned*)&h01;
            ph23[ni] = *(unsigned*)&h23;
        }
        ps0 += __shfl_xor_sync(0xffffffff, ps0, 1);
        ps0 += __shfl_xor_sync(0xffffffff, ps0, 2);
        ps1 += __shfl_xor_sync(0xffffffff, ps1, 1);
        ps1 += __shfl_xor_sync(0xffffffff, ps1, 2);
        l0 = l0 * al0 + ps0;
        l1 = l1 * al1 + ps1;

        // O = O*alpha + P @ V
#pragma unroll
        for (int ni = 0; ni < 8; ni++) {
            o[ni][0] *= al0; o[ni][1] *= al0;
            o[ni][2] *= al1; o[ni][3] *= al1;
        }
#pragma unroll
        for (int kc = 0; kc < 4; kc++) {
            unsigned a[4] = {ph01[2*kc], ph23[2*kc], ph01[2*kc+1], ph23[2*kc+1]};
#pragma unroll
            for (int ni = 0; ni < 8; ni++) {
                int cb = ni * 8 + gr;
                unsigned b[2];
                b[0] = V2[kc * 8 + tc][cb];
                b[1] = V2[kc * 8 + tc + 4][cb];
                mma_f16(o[ni], a, b);
            }
        }
        __syncthreads();
    }

    // normalize + write pre-split bf16 concat output
    float inv0 = (l0 > 0.f) ? 1.f / l0 : 0.f;
    float inv1 = (l1 > 0.f) ? 1.f / l1 : 0.f;
#pragma unroll
    for (int ni = 0; ni < 8; ni++) {
        int cl = h * MM + ni * 8 + 2 * tc;
        int r0 = q0 + wr + gr;
        float v0 = o[ni][0] * inv0, v1 = o[ni][1] * inv0;
        float v2 = o[ni][2] * inv1, v3 = o[ni][3] * inv1;
        __nv_bfloat16 h0, l0b, h1, l1b;
        split_bf(v0, h0, l0b); split_bf(v1, h1, l1b);
        *(unsigned*)&g_Oh[(size_t)r0 * (HH * MM) + cl] = pack_bf2(h0, h1);
        *(unsigned*)&g_Ol[(size_t)r0 * (HH * MM) + cl] = pack_bf2(l0b, l1b);
        split_bf(v2, h0, l0b); split_bf(v3, h1, l1b);
        *(unsigned*)&g_Oh[(size_t)(r0 + 8) * (HH * MM) + cl] = pack_bf2(h0, h1);
        *(unsigned*)&g_Ol[(size_t)(r0 + 8) * (HH * MM) + cl] = pack_bf2(l0b, l1b);
    }
}

// ---------------------------------------------------------------------------
extern "C" void kernel_launch(void* const* d_in, const int* in_sizes, int n_in,
                              void* d_out, int out_size)
{
    const float* x    = (const float*)d_in[0];
    const float* z    = (const float*)d_in[1];
    const int*   mask = (const int*)  d_in[2];
    const float* Wq   = (const float*)d_in[3];
    const float* bq   = (const float*)d_in[4];
    const float* Wk   = (const float*)d_in[5];
    const float* bk   = (const float*)d_in[6];
    const float* Wv   = (const float*)d_in[7];
    const float* bv   = (const float*)d_in[8];
    const float* W0   = (const float*)d_in[9];
    const float* b0   = (const float*)d_in[10];
    float* out = (float*)d_out;

    static bool attr_set = false;
    if (!attr_set) {
        cudaFuncSetAttribute(qkv_kernel, cudaFuncAttributeMaxDynamicSharedMemorySize,
                             PROJ_SMEM_BYTES);
        cudaFuncSetAttribute(out_proj_kernel, cudaFuncAttributeMaxDynamicSharedMemorySize,
                             PROJ_SMEM_BYTES);
        cudaFuncSetAttribute(attn_kernel, cudaFuncAttributeMaxDynamicSharedMemorySize,
                             ATTN_SMEM_BYTES);
        attr_set = true;
    }

    split_xz_kernel<<<SS * EE / 1024, 256>>>(x, z);
    pack_w_kernel<<<3 * HH * 512 * 64 / 256, 256>>>(Wq, Wk, Wv);
    pack_w0_kernel<<<512 * OO / 256, 256>>>(W0);

    qkv_kernel<<<dim3(SS/128, HH, 3), 256, PROJ_SMEM_BYTES>>>(bq, bk, bv);
    attn_kernel<<<dim3(SS/128, HH), 256, ATTN_SMEM_BYTES>>>(mask);
    out_proj_kernel<<<dim3(SS/128, OO/64), 256, PROJ_SMEM_BYTES>>>(b0, out);
}

// round 5
// speedup vs baseline: 4.4864x; 1.1578x over previous
#include <cuda_runtime.h>
#include <cuda_bf16.h>
#include <cuda_fp16.h>
#include <math.h>

#define HH 16
#define EE 1024
#define DD 64
#define MM 64
#define OO 1024
#define SS 2048

// ---------------------------------------------------------------------------
// Device-global scratch
// ---------------------------------------------------------------------------
__device__ __align__(16) __nv_bfloat16 g_xh[SS * EE], g_xl[SS * EE];
__device__ __align__(16) __nv_bfloat16 g_zh[SS * EE], g_zl[SS * EE];
__device__ __align__(16) __nv_bfloat16 g_Wth[3 * 1024 * 1024], g_Wtl[3 * 1024 * 1024]; // [kind][n][k]
__device__ __align__(16) __nv_bfloat16 g_W0th[1024 * 1024], g_W0tl[1024 * 1024];       // [n=o][k=hm]
__device__ __align__(16) __half g_Q16[HH * SS * DD];
__device__ __align__(16) __half g_K16[HH * SS * DD];
__device__ __align__(16) __half g_V16[HH * SS * MM];
__device__ __align__(16) __nv_bfloat16 g_Oh[SS * HH * MM], g_Ol[SS * HH * MM];

// ---------------------------------------------------------------------------
// helpers
// ---------------------------------------------------------------------------
__device__ __forceinline__ unsigned pack_bf2(__nv_bfloat16 a, __nv_bfloat16 b) {
    __nv_bfloat162 h; h.x = a; h.y = b;
    return *reinterpret_cast<unsigned*>(&h);
}
__device__ __forceinline__ void split_bf(float x, __nv_bfloat16& hi, __nv_bfloat16& lo) {
    hi = __float2bfloat16_rn(x);
    lo = __float2bfloat16_rn(x - __bfloat162float(hi));
}
__device__ __forceinline__ void mma_bf16(float* d, const unsigned* a, const unsigned* b) {
    asm volatile(
        "mma.sync.aligned.m16n8k16.row.col.f32.bf16.bf16.f32 "
        "{%0,%1,%2,%3}, {%4,%5,%6,%7}, {%8,%9}, {%0,%1,%2,%3};"
        : "+f"(d[0]), "+f"(d[1]), "+f"(d[2]), "+f"(d[3])
        : "r"(a[0]), "r"(a[1]), "r"(a[2]), "r"(a[3]), "r"(b[0]), "r"(b[1]));
}
__device__ __forceinline__ void mma_f16(float* d, const unsigned* a, const unsigned* b) {
    asm volatile(
        "mma.sync.aligned.m16n8k16.row.col.f32.f16.f16.f32 "
        "{%0,%1,%2,%3}, {%4,%5,%6,%7}, {%8,%9}, {%0,%1,%2,%3};"
        : "+f"(d[0]), "+f"(d[1]), "+f"(d[2]), "+f"(d[3])
        : "r"(a[0]), "r"(a[1]), "r"(a[2]), "r"(a[3]), "r"(b[0]), "r"(b[1]));
}
__device__ __forceinline__ void ldsm4(unsigned* r, unsigned a) {
    asm volatile("ldmatrix.sync.aligned.m8n8.x4.shared.b16 {%0,%1,%2,%3}, [%4];"
        : "=r"(r[0]), "=r"(r[1]), "=r"(r[2]), "=r"(r[3]) : "r"(a));
}
__device__ __forceinline__ void ldsm4t(unsigned* r, unsigned a) {
    asm volatile("ldmatrix.sync.aligned.m8n8.x4.trans.shared.b16 {%0,%1,%2,%3}, [%4];"
        : "=r"(r[0]), "=r"(r[1]), "=r"(r[2]), "=r"(r[3]) : "r"(a));
}
__device__ __forceinline__ void cpa16(unsigned d, const void* s) {
    asm volatile("cp.async.cg.shared.global [%0], [%1], 16;" :: "r"(d), "l"(s));
}
__device__ __forceinline__ unsigned smem_u32(const void* p) {
    return (unsigned)__cvta_generic_to_shared(p);
}

// ---------------------------------------------------------------------------
// Prepass kernels
// ---------------------------------------------------------------------------
__global__ void split_xz_kernel(const float* __restrict__ x, const float* __restrict__ z)
{
    int i = (blockIdx.x * 256 + threadIdx.x) * 4;
    float4 vx = *(const float4*)&x[i];
    float4 vz = *(const float4*)&z[i];
    const float* px = (const float*)&vx;
    const float* pz = (const float*)&vz;
#pragma unroll
    for (int j = 0; j < 4; j++) {
        __nv_bfloat16 h, l;
        split_bf(px[j], h, l); g_xh[i + j] = h; g_xl[i + j] = l;
        split_bf(pz[j], h, l); g_zh[i + j] = h; g_zl[i + j] = l;
    }
}

// Wq/Wk/Wv [H][E][64] -> transposed split [kind][n=h*64+d][k=e]
__global__ void pack_w_kernel(const float* __restrict__ Wq,
                              const float* __restrict__ Wk,
                              const float* __restrict__ Wv)
{
    __shared__ float ts[64][65];
    const int kind = blockIdx.z, h = blockIdx.y, e0 = blockIdx.x * 64;
    const float* W = (kind == 0) ? Wq : (kind == 1) ? Wk : Wv;
    const int r = threadIdx.x >> 4, c4 = (threadIdx.x & 15) * 4;
#pragma unroll
    for (int i = 0; i < 4; i++) {
        int rr = r + i * 16;
        float4 v = *(const float4*)&W[((size_t)h * EE + e0 + rr) * 64 + c4];
        ts[rr][c4 + 0] = v.x; ts[rr][c4 + 1] = v.y;
        ts[rr][c4 + 2] = v.z; ts[rr][c4 + 3] = v.w;
    }
    __syncthreads();
    __nv_bfloat16* outh = g_Wth + (size_t)kind * 1024 * 1024;
    __nv_bfloat16* outl = g_Wtl + (size_t)kind * 1024 * 1024;
#pragma unroll
    for (int i = 0; i < 4; i++) {
        int d = r + i * 16;
        size_t idx = ((size_t)(h * 64 + d)) * 1024 + e0 + c4;
        __nv_bfloat16 h0, l0, h1, l1, h2, l2, h3, l3;
        split_bf(ts[c4 + 0][d], h0, l0); split_bf(ts[c4 + 1][d], h1, l1);
        split_bf(ts[c4 + 2][d], h2, l2); split_bf(ts[c4 + 3][d], h3, l3);
        uint2 uh = {pack_bf2(h0, h1), pack_bf2(h2, h3)};
        uint2 ul = {pack_bf2(l0, l1), pack_bf2(l2, l3)};
        *(uint2*)&outh[idx] = uh;
        *(uint2*)&outl[idx] = ul;
    }
}

// W0 [1024 k=hm][1024 o] -> transposed split [n=o][k=hm]
__global__ void pack_w0_kernel(const float* __restrict__ W0)
{
    __shared__ float ts[64][65];
    const int k0 = blockIdx.x * 64, o0 = blockIdx.y * 64;
    const int r = threadIdx.x >> 4, c4 = (threadIdx.x & 15) * 4;
#pragma unroll
    for (int i = 0; i < 4; i++) {
        int rr = r + i * 16;
        float4 v = *(const float4*)&W0[(size_t)(k0 + rr) * OO + o0 + c4];
        ts[rr][c4 + 0] = v.x; ts[rr][c4 + 1] = v.y;
        ts[rr][c4 + 2] = v.z; ts[rr][c4 + 3] = v.w;
    }
    __syncthreads();
#pragma unroll
    for (int i = 0; i < 4; i++) {
        int d = r + i * 16;
        size_t idx = ((size_t)(o0 + d)) * 1024 + k0 + c4;
        __nv_bfloat16 h0, l0, h1, l1, h2, l2, h3, l3;
        split_bf(ts[c4 + 0][d], h0, l0); split_bf(ts[c4 + 1][d], h1, l1);
        split_bf(ts[c4 + 2][d], h2, l2); split_bf(ts[c4 + 3][d], h3, l3);
        uint2 uh = {pack_bf2(h0, h1), pack_bf2(h2, h3)};
        uint2 ul = {pack_bf2(l0, l1), pack_bf2(l2, l3)};
        *(uint2*)&g_W0th[idx] = uh;
        *(uint2*)&g_W0tl[idx] = ul;
    }
}

// ---------------------------------------------------------------------------
// Split-bf16 GEMM core with cp.async double buffer + ldmatrix.
// C tile 128x128, BK=64, 256 threads, 8 warps (warp tile 32x64).
// Stage layout (73728 B): Ah[128][72] Al Bh[128][72] Bl. 2 stages = 147456 B.
// ---------------------------------------------------------------------------
#define STAGE_BYTES 73728
#define GEMM_SMEM_BYTES (2 * STAGE_BYTES)

__device__ __forceinline__ void gemm_core(
    const __nv_bfloat16* __restrict__ Agh, const __nv_bfloat16* __restrict__ Agl,
    const __nv_bfloat16* __restrict__ Bgh, const __nv_bfloat16* __restrict__ Bgl,
    int row0, int n0, float acc[2][8][4], char* smraw)
{
    const int tid  = threadIdx.x;
    const int lane = tid & 31;
    const int warp = tid >> 5;
    const int wm = (warp >> 1) * 32;
    const int wn = (warp & 1) * 64;

    const int cr = tid >> 3;          // 0..31
    const int cc = (tid & 7) * 8;     // halves

    const int a_off = (lane & 15) * 144 + (lane >> 4) * 16;
    const int b_off = (((lane >> 4) << 3) + (lane & 7)) * 144 + ((lane >> 3) & 1) * 16;

    const unsigned sm0 = smem_u32(smraw);

#pragma unroll
    for (int mi = 0; mi < 2; mi++)
#pragma unroll
        for (int ni = 0; ni < 8; ni++)
#pragma unroll
            for (int j = 0; j < 4; j++) acc[mi][ni][j] = 0.f;

    // prologue: stage 0
    {
        unsigned st = sm0;
#pragma unroll
        for (int i = 0; i < 4; i++) {
            int r = cr + i * 32;
            unsigned ro = r * 144 + cc * 2;
            cpa16(st + ro,          Agh + (size_t)(row0 + r) * 1024 + cc);
            cpa16(st + 18432 + ro,  Agl + (size_t)(row0 + r) * 1024 + cc);
            cpa16(st + 36864 + ro,  Bgh + (size_t)(n0 + r) * 1024 + cc);
            cpa16(st + 55296 + ro,  Bgl + (size_t)(n0 + r) * 1024 + cc);
        }
        asm volatile("cp.async.commit_group;");
    }

    const int NK = EE / 64;  // 16
    for (int it = 0; it < NK; it++) {
        int cur = it & 1;
        if (it + 1 < NK) {
            unsigned st = sm0 + (cur ^ 1) * STAGE_BYTES;
            int k0 = (it + 1) * 64;
#pragma unroll
            for (int i = 0; i < 4; i++) {
                int r = cr + i * 32;
                unsigned ro = r * 144 + cc * 2;
                cpa16(st + ro,          Agh + (size_t)(row0 + r) * 1024 + k0 + cc);
                cpa16(st + 18432 + ro,  Agl + (size_t)(row0 + r) * 1024 + k0 + cc);
                cpa16(st + 36864 + ro,  Bgh + (size_t)(n0 + r) * 1024 + k0 + cc);
                cpa16(st + 55296 + ro,  Bgl + (size_t)(n0 + r) * 1024 + k0 + cc);
            }
            asm volatile("cp.async.commit_group;");
            asm volatile("cp.async.wait_group 1;");
        } else {
            asm volatile("cp.async.wait_group 0;");
        }
        __syncthreads();

        // compute on stage cur
        {
            unsigned st = sm0 + cur * STAGE_BYTES;
            unsigned aH = st + a_off + wm * 144;
            unsigned aL = aH + 18432;
            unsigned bH = st + 36864 + b_off + wn * 144;
            unsigned bL = bH + 18432;
#pragma unroll
            for (int kc = 0; kc < 4; kc++) {
                const int ko = kc * 32;   // bytes for 16 halves
                unsigned ah[2][4], al[2][4];
                ldsm4(ah[0], aH + ko);
                ldsm4(ah[1], aH + 16 * 144 + ko);
                ldsm4(al[0], aL + ko);
                ldsm4(al[1], aL + 16 * 144 + ko);
                unsigned bh[8][2], bl[8][2];
#pragma unroll
                for (int j = 0; j < 4; j++) {
                    unsigned t4[4];
                    ldsm4(t4, bH + j * 16 * 144 + ko);
                    bh[2*j][0] = t4[0]; bh[2*j][1] = t4[1];
                    bh[2*j+1][0] = t4[2]; bh[2*j+1][1] = t4[3];
                    ldsm4(t4, bL + j * 16 * 144 + ko);
                    bl[2*j][0] = t4[0]; bl[2*j][1] = t4[1];
                    bl[2*j+1][0] = t4[2]; bl[2*j+1][1] = t4[3];
                }
#pragma unroll
                for (int mi = 0; mi < 2; mi++)
#pragma unroll
                    for (int ni = 0; ni < 8; ni++) {
                        mma_bf16(acc[mi][ni], ah[mi], bl[ni]);
                        mma_bf16(acc[mi][ni], al[mi], bh[ni]);
                        mma_bf16(acc[mi][ni], ah[mi], bh[ni]);
                    }
            }
        }
        __syncthreads();
    }
}

// ---------------------------------------------------------------------------
// QKV: grid (16, 8, 3). C tile 128 rows x 128 n-cols (2 heads). fp16 out.
// ---------------------------------------------------------------------------
__global__ __launch_bounds__(256, 1) void qkv_kernel(
    const float* __restrict__ bq, const float* __restrict__ bk,
    const float* __restrict__ bv)
{
    extern __shared__ char smraw[];
    const int kind = blockIdx.z;
    const int row0 = blockIdx.x * 128;
    const int bn0  = blockIdx.y * 128;

    const __nv_bfloat16* Agh = (kind == 0) ? g_xh : g_zh;
    const __nv_bfloat16* Agl = (kind == 0) ? g_xl : g_zl;
    const __nv_bfloat16* Bgh = g_Wth + (size_t)kind * 1024 * 1024;
    const __nv_bfloat16* Bgl = g_Wtl + (size_t)kind * 1024 * 1024;
    const float* bias = (kind == 0) ? bq : (kind == 1) ? bk : bv;
    __half* Cbase = (kind == 0) ? g_Q16 : (kind == 1) ? g_K16 : g_V16;

    float acc[2][8][4];
    gemm_core(Agh, Agl, Bgh, Bgl, row0, bn0, acc, smraw);

    const int lane = threadIdx.x & 31;
    const int warp = threadIdx.x >> 5;
    const int gr = lane >> 2, tc = lane & 3;
    const int wm = (warp >> 1) * 32, wn = (warp & 1) * 64;
#pragma unroll
    for (int mi = 0; mi < 2; mi++)
#pragma unroll
        for (int ni = 0; ni < 8; ni++) {
            int nglob = bn0 + wn + ni * 8 + 2 * tc;
            int hh = nglob >> 6, d = nglob & 63;
            int r0 = row0 + wm + mi * 16 + gr;
            float b0v = bias[hh * 64 + d], b1v = bias[hh * 64 + d + 1];
            __half* C = Cbase + ((size_t)hh * SS) * 64 + d;
            *(__half2*)&C[(size_t)r0 * 64] =
                __floats2half2_rn(acc[mi][ni][0] + b0v, acc[mi][ni][1] + b1v);
            *(__half2*)&C[(size_t)(r0 + 8) * 64] =
                __floats2half2_rn(acc[mi][ni][2] + b0v, acc[mi][ni][3] + b1v);
        }
}

// ---------------------------------------------------------------------------
// Output projection: grid (16, 8)
// ---------------------------------------------------------------------------
__global__ __launch_bounds__(256, 1) void out_proj_kernel(
    const float* __restrict__ b0, float* __restrict__ out)
{
    extern __shared__ char smraw[];
    const int row0 = blockIdx.x * 128;
    const int bn0  = blockIdx.y * 128;

    float acc[2][8][4];
    gemm_core(g_Oh, g_Ol, g_W0th, g_W0tl, row0, bn0, acc, smraw);

    const int lane = threadIdx.x & 31;
    const int warp = threadIdx.x >> 5;
    const int gr = lane >> 2, tc = lane & 3;
    const int wm = (warp >> 1) * 32, wn = (warp & 1) * 64;
#pragma unroll
    for (int mi = 0; mi < 2; mi++)
#pragma unroll
        for (int ni = 0; ni < 8; ni++) {
            int nglob = bn0 + wn + ni * 8 + 2 * tc;
            int r0 = row0 + wm + mi * 16 + gr;
            float b0v = b0[nglob], b1v = b0[nglob + 1];
            float2 v0 = {acc[mi][ni][0] + b0v, acc[mi][ni][1] + b1v};
            float2 v1 = {acc[mi][ni][2] + b0v, acc[mi][ni][3] + b1v};
            *(float2*)&out[(size_t)r0 * OO + nglob] = v0;
            *(float2*)&out[(size_t)(r0 + 8) * OO + nglob] = v1;
        }
}

// ---------------------------------------------------------------------------
// Flash attention, fp16 MMA, ldmatrix operands, register P.
// grid (S/128, H), 256 threads. smem 36864 B: Qs[128][72] Ks[64][72] Vs[64][72]
// ---------------------------------------------------------------------------
#define ATTN_SMEM_BYTES (128 * 72 * 2 + 64 * 72 * 2 + 64 * 72 * 2)

__global__ __launch_bounds__(256, 1) void attn_kernel(const int* __restrict__ mask)
{
    extern __shared__ char smraw[];
    __half (*Qs)[72] = (__half(*)[72])(smraw);
    __half (*Ks)[72] = (__half(*)[72])(smraw + 128 * 72 * 2);
    __half (*Vs)[72] = (__half(*)[72])(smraw + 128 * 72 * 2 + 64 * 72 * 2);

    const int h  = blockIdx.y;
    const int q0 = blockIdx.x * 128;
    const int tid  = threadIdx.x;
    const int lane = tid & 31;
    const int warp = tid >> 5;
    const int gr = lane >> 2, tc = lane & 3;
    const int wr = warp * 16;

    const __half* Qg = g_Q16 + (size_t)h * SS * 64;
    const __half* Kg = g_K16 + (size_t)h * SS * 64;
    const __half* Vg = g_V16 + (size_t)h * SS * 64;

    // Q tile load
    {
        int r = tid >> 1, s = (tid & 1) * 32;
        const float4* src = (const float4*)(Qg + (size_t)(q0 + r) * 64 + s);
        float4* dst = (float4*)&Qs[r][s];
#pragma unroll
        for (int j = 0; j < 4; j++) dst[j] = src[j];
    }

    float o[8][4];
#pragma unroll
    for (int ni = 0; ni < 8; ni++)
#pragma unroll
        for (int j = 0; j < 4; j++) o[ni][j] = 0.f;
    float m0 = -1e30f, m1 = -1e30f, l0 = 0.f, l1 = 0.f;

    __syncthreads();

    // hoist Q fragments (loop invariant)
    const unsigned qs_u = smem_u32(&Qs[0][0]);
    const unsigned ks_u = smem_u32(&Ks[0][0]);
    const unsigned vs_u = smem_u32(&Vs[0][0]);
    unsigned qf[4][4];
    {
        unsigned qa = qs_u + (wr + (lane & 15)) * 144 + (lane >> 4) * 16;
#pragma unroll
        for (int kc = 0; kc < 4; kc++) ldsm4(qf[kc], qa + kc * 32);
    }
    const unsigned kb_off = ks_u + (((lane >> 4) << 3) + (lane & 7)) * 144 + ((lane >> 3) & 1) * 16;
    const unsigned vb_off = vs_u + ((((lane >> 3) & 1) << 3) + (lane & 7)) * 144 + ((lane >> 4) << 3) * 2;

    for (int t0 = 0; t0 < SS; t0 += 64) {
        // K,V tiles: 64 rows x 64 halves each
        {
            int r = tid >> 3, c8 = (tid & 7) * 8;
            const uint4 k0v = *(const uint4*)(Kg + (size_t)(t0 + r) * 64 + c8);
            const uint4 k1v = *(const uint4*)(Kg + (size_t)(t0 + r + 32) * 64 + c8);
            const uint4 v0v = *(const uint4*)(Vg + (size_t)(t0 + r) * 64 + c8);
            const uint4 v1v = *(const uint4*)(Vg + (size_t)(t0 + r + 32) * 64 + c8);
            *(uint4*)&Ks[r][c8] = k0v;
            *(uint4*)&Ks[r + 32][c8] = k1v;
            *(uint4*)&Vs[r][c8] = v0v;
            *(uint4*)&Vs[r + 32][c8] = v1v;
        }
        __syncthreads();

        // S = Q @ K^T
        float s[8][4];
#pragma unroll
        for (int ni = 0; ni < 8; ni++)
#pragma unroll
            for (int j = 0; j < 4; j++) s[ni][j] = 0.f;

#pragma unroll
        for (int kc = 0; kc < 4; kc++) {
#pragma unroll
            for (int j = 0; j < 4; j++) {
                unsigned t4[4];
                ldsm4(t4, kb_off + j * 16 * 144 + kc * 32);
                mma_f16(s[2*j],     qf[kc], t4);
                mma_f16(s[2*j + 1], qf[kc], t4 + 2);
            }
        }

        // scale + additive mask
        const int r0g = q0 + wr + gr;
        const int r1g = r0g + 8;
#pragma unroll
        for (int ni = 0; ni < 8; ni++) {
            int cg = t0 + ni * 8 + 2 * tc;
            int2 mk0 = *(const int2*)&mask[(size_t)r0g * SS + cg];
            int2 mk1 = *(const int2*)&mask[(size_t)r1g * SS + cg];
            s[ni][0] = s[ni][0] * 0.125f + (mk0.x ? 0.f : -1e30f);
            s[ni][1] = s[ni][1] * 0.125f + (mk0.y ? 0.f : -1e30f);
            s[ni][2] = s[ni][2] * 0.125f + (mk1.x ? 0.f : -1e30f);
            s[ni][3] = s[ni][3] * 0.125f + (mk1.y ? 0.f : -1e30f);
        }

        // online softmax
        float pm0 = -1e30f, pm1 = -1e30f;
#pragma unroll
        for (int ni = 0; ni < 8; ni++) {
            pm0 = fmaxf(pm0, fmaxf(s[ni][0], s[ni][1]));
            pm1 = fmaxf(pm1, fmaxf(s[ni][2], s[ni][3]));
        }
        pm0 = fmaxf(pm0, __shfl_xor_sync(0xffffffff, pm0, 1));
        pm0 = fmaxf(pm0, __shfl_xor_sync(0xffffffff, pm0, 2));
        pm1 = fmaxf(pm1, __shfl_xor_sync(0xffffffff, pm1, 1));
        pm1 = fmaxf(pm1, __shfl_xor_sync(0xffffffff, pm1, 2));
        float nm0 = fmaxf(m0, pm0), nm1 = fmaxf(m1, pm1);
        float al0 = __expf(m0 - nm0);
        float al1 = __expf(m1 - nm1);
        m0 = nm0; m1 = nm1;

        unsigned ph01[8], ph23[8];
        float ps0 = 0.f, ps1 = 0.f;
#pragma unroll
        for (int ni = 0; ni < 8; ni++) {
            float p0 = __expf(s[ni][0] - m0);
            float p1 = __expf(s[ni][1] - m0);
            float p2 = __expf(s[ni][2] - m1);
            float p3 = __expf(s[ni][3] - m1);
            ps0 += p0 + p1;  ps1 += p2 + p3;
            __half2 h01 = __floats2half2_rn(p0, p1);
            __half2 h23 = __floats2half2_rn(p2, p3);
            ph01[ni] = *(unsigned*)&h01;
            ph23[ni] = *(unsigned*)&h23;
        }
        ps0 += __shfl_xor_sync(0xffffffff, ps0, 1);
        ps0 += __shfl_xor_sync(0xffffffff, ps0, 2);
        ps1 += __shfl_xor_sync(0xffffffff, ps1, 1);
        ps1 += __shfl_xor_sync(0xffffffff, ps1, 2);
        l0 = l0 * al0 + ps0;
        l1 = l1 * al1 + ps1;

#pragma unroll
        for (int ni = 0; ni < 8; ni++) {
            o[ni][0] *= al0; o[ni][1] *= al0;
            o[ni][2] *= al1; o[ni][3] *= al1;
        }
        // O += P @ V (A from registers, B via ldmatrix.trans)
#pragma unroll
        for (int kc = 0; kc < 4; kc++) {
            unsigned a[4] = {ph01[2*kc], ph23[2*kc], ph01[2*kc+1], ph23[2*kc+1]};
#pragma unroll
            for (int j = 0; j < 4; j++) {
                unsigned t4[4];
                ldsm4t(t4, vb_off + kc * 16 * 144 + j * 32);
                mma_f16(o[2*j],     a, t4);
                mma_f16(o[2*j + 1], a, t4 + 2);
            }
        }
        __syncthreads();
    }

    // normalize + write pre-split bf16 concat output
    float inv0 = (l0 > 0.f) ? 1.f / l0 : 0.f;
    float inv1 = (l1 > 0.f) ? 1.f / l1 : 0.f;
#pragma unroll
    for (int ni = 0; ni < 8; ni++) {
        int cl = h * MM + ni * 8 + 2 * tc;
        int r0 = q0 + wr + gr;
        float v0 = o[ni][0] * inv0, v1 = o[ni][1] * inv0;
        float v2 = o[ni][2] * inv1, v3 = o[ni][3] * inv1;
        __nv_bfloat16 h0, l0b, h1, l1b;
        split_bf(v0, h0, l0b); split_bf(v1, h1, l1b);
        *(unsigned*)&g_Oh[(size_t)r0 * (HH * MM) + cl] = pack_bf2(h0, h1);
        *(unsigned*)&g_Ol[(size_t)r0 * (HH * MM) + cl] = pack_bf2(l0b, l1b);
        split_bf(v2, h0, l0b); split_bf(v3, h1, l1b);
        *(unsigned*)&g_Oh[(size_t)(r0 + 8) * (HH * MM) + cl] = pack_bf2(h0, h1);
        *(unsigned*)&g_Ol[(size_t)(r0 + 8) * (HH * MM) + cl] = pack_bf2(l0b, l1b);
    }
}

// ---------------------------------------------------------------------------
extern "C" void kernel_launch(void* const* d_in, const int* in_sizes, int n_in,
                              void* d_out, int out_size)
{
    const float* x    = (const float*)d_in[0];
    const float* z    = (const float*)d_in[1];
    const int*   mask = (const int*)  d_in[2];
    const float* Wq   = (const float*)d_in[3];
    const float* bq   = (const float*)d_in[4];
    const float* Wk   = (const float*)d_in[5];
    const float* bk   = (const float*)d_in[6];
    const float* Wv   = (const float*)d_in[7];
    const float* bv   = (const float*)d_in[8];
    const float* W0   = (const float*)d_in[9];
    const float* b0   = (const float*)d_in[10];
    float* out = (float*)d_out;

    static bool attr_set = false;
    if (!attr_set) {
        cudaFuncSetAttribute(qkv_kernel, cudaFuncAttributeMaxDynamicSharedMemorySize,
                             GEMM_SMEM_BYTES);
        cudaFuncSetAttribute(out_proj_kernel, cudaFuncAttributeMaxDynamicSharedMemorySize,
                             GEMM_SMEM_BYTES);
        cudaFuncSetAttribute(attn_kernel, cudaFuncAttributeMaxDynamicSharedMemorySize,
                             ATTN_SMEM_BYTES);
        attr_set = true;
    }

    split_xz_kernel<<<SS * EE / 1024, 256>>>(x, z);
    pack_w_kernel<<<dim3(16, HH, 3), 256>>>(Wq, Wk, Wv);
    pack_w0_kernel<<<dim3(16, 16), 256>>>(W0);

    qkv_kernel<<<dim3(SS / 128, 8, 3), 256, GEMM_SMEM_BYTES>>>(bq, bk, bv);
    attn_kernel<<<dim3(SS / 128, HH), 256, ATTN_SMEM_BYTES>>>(mask);
    out_proj_kernel<<<dim3(SS / 128, 8), 256, GEMM_SMEM_BYTES>>>(b0, out);
}